// round 13
// baseline (speedup 1.0000x reference)
#include <cuda_runtime.h>
#include <cstdint>

// Problem constants
#define Nn   4096
#define Bb   4
#define Ff   32
#define NF   (Nn * Ff)        // 131072
#define BNF  (Bb * Nn * Ff)   // 524288
#define CC   256              // 2 sources * B * F columns in aggregation GEMM

// Scratch (no allocs allowed -> device globals)
__device__ float g_agg[Nn * CC];                       // 4 MB
__device__ float g_part[2 * Nn * CC];                  // 8 MB (k-split partials)
__device__ float g_h1[BNF];                            // 2 MB
__device__ __align__(16) float g_Bt[CC * Nn];          // 4 MB rhs fp32, [j][k]
__device__ __align__(16) float g_Wt[14 * 64 * 32];     // W transposed: [conv][j][k]

// ---------------------------------------------------------------------------
// Helpers
// ---------------------------------------------------------------------------
__device__ __forceinline__ uint32_t smem_u32(const void* p) {
    uint32_t a;
    asm("{ .reg .u64 t; cvta.to.shared.u64 t, %1; cvt.u32.u64 %0, t; }"
        : "=r"(a) : "l"(p));
    return a;
}
__device__ __forceinline__ void cpa16(uint32_t s, const void* g) {
    asm volatile("cp.async.cg.shared.global [%0], [%1], 16;" :: "r"(s), "l"(g));
}
#define CP_COMMIT() asm volatile("cp.async.commit_group;" ::: "memory")
#define CP_WAIT0()  asm volatile("cp.async.wait_group 0;" ::: "memory")

#define LDSM_X4(r0, r1, r2, r3, a) \
    asm volatile("ldmatrix.sync.aligned.m8n8.x4.shared.b16 {%0,%1,%2,%3}, [%4];" \
                 : "=r"(r0), "=r"(r1), "=r"(r2), "=r"(r3) : "r"(a))

__device__ __forceinline__ void mma1688(float* c, const uint32_t* a,
                                        uint32_t b0, uint32_t b1) {
    asm volatile(
        "mma.sync.aligned.m16n8k8.row.col.f32.tf32.tf32.f32 "
        "{%0,%1,%2,%3}, {%4,%5,%6,%7}, {%8,%9}, {%0,%1,%2,%3};"
        : "+f"(c[0]), "+f"(c[1]), "+f"(c[2]), "+f"(c[3])
        : "r"(a[0]), "r"(a[1]), "r"(a[2]), "r"(a[3]), "r"(b0), "r"(b1));
}

// Exact register split: hi = trunc-to-tf32(a), lo = (a-hi) masked to tf32.
__device__ __forceinline__ void tsplit2(uint32_t r, uint32_t& h, uint32_t& l) {
    h = r & 0xFFFFE000u;
    float lf = __uint_as_float(r) - __uint_as_float(h);
    l = __float_as_uint(lf) & 0xFFFFE000u;
}

__device__ __forceinline__ float sigm(float x) {
    return 1.0f / (1.0f + __expf(-x));
}

// ---------------------------------------------------------------------------
// prep_Wt: g_Wt[(c*64+j)*32 + k] = W[(c*32+k)*64 + j]
// ---------------------------------------------------------------------------
__global__ __launch_bounds__(256)
void prep_Wt(const float* __restrict__ W) {
    int i = blockIdx.x * 256 + threadIdx.x;    // 0..28671
    if (i < 14 * 64 * 32) {
        int c = i >> 11;
        int rem = i & 2047;
        int j = rem >> 5;
        int k = rem & 31;
        g_Wt[i] = W[(c * 32 + k) * 64 + j];
    }
}

// ---------------------------------------------------------------------------
// conv_rhs: build Bt[j][k] = src[b][k][f] (j = src*128 + b*32 + f), raw fp32
// ---------------------------------------------------------------------------
__global__ __launch_bounds__(256)
void conv_rhs(const float* __restrict__ s0in, const float* __restrict__ s1,
              int s0_is_h1) {
    __shared__ float t[64][33];
    const int tid = threadIdx.x;
    const int src = blockIdx.y >> 2;
    const int b   = blockIdx.y & 3;
    const int k0  = blockIdx.x * 64;

    const float* s0 = s0_is_h1 ? (const float*)g_h1 : s0in;
    const float* sp = (src == 0) ? s0 : s1;
    const float* base = sp + b * NF + k0 * Ff;

    #pragma unroll
    for (int i = 0; i < 2; i++) {
        int fi = tid + 256 * i;
        int row = fi >> 3, quad = fi & 7;
        float4 v = *(const float4*)(base + row * Ff + quad * 4);
        t[row][quad * 4 + 0] = v.x; t[row][quad * 4 + 1] = v.y;
        t[row][quad * 4 + 2] = v.z; t[row][quad * 4 + 3] = v.w;
    }
    __syncthreads();

    const int j0 = src * 128 + b * Ff;
    #pragma unroll
    for (int i = 0; i < 2; i++) {
        int oi = tid + 256 * i;
        int f  = oi >> 4;
        int kq = oi & 15;
        float4 v = make_float4(t[kq * 4 + 0][f], t[kq * 4 + 1][f],
                               t[kq * 4 + 2][f], t[kq * 4 + 3][f]);
        *(float4*)(g_Bt + (long long)(j0 + f) * Nn + k0 + kq * 4) = v;
    }
}

// ---------------------------------------------------------------------------
// agg_mma: g_part[ks][m][j] = sum_{k in ks range} adj[m][k] * S[k][j]
// tf32 3-pass register-split GEMM. CTA tile 128(M) x 64(N), K-chunk 32,
// 2-stage cp.async, 2 CTAs/SM (small tile + capped regs so bubbles overlap).
// 8 warps 4m x 2n -> warp tile 32x32. Grid (32 mt, 4 nt, 2 ks) = 256 CTAs.
// ---------------------------------------------------------------------------
#define AROWB 144                   // 32 fp32 = 128B + 16B pad
#define A_O   0
#define B_O   (128 * AROWB)         // 18432
#define STG_B (128 * AROWB + 64 * AROWB)   // 27648
#define AGG_SMEM (2 * STG_B)        // 55296

__global__ __launch_bounds__(256, 2)
void agg_mma(const float* __restrict__ Araw) {
    extern __shared__ __align__(16) char dsm[];
    const uint32_t sm0 = smem_u32(dsm);

    const int tid  = threadIdx.x;
    const int wid  = tid >> 5;
    const int lane = tid & 31;
    const int m0   = blockIdx.x * 128;
    const int n0   = blockIdx.y * 64;
    const int ksz  = blockIdx.z;
    const int kbase = ksz * 2048;

    const int wm = wid & 3;         // warp m (32 rows)
    const int wn = wid >> 2;        // warp n (32 cols)
    const int t  = lane & 3;
    const int g  = lane >> 2;

    const int a_off = (wm * 32 + (lane & 15)) * AROWB + (lane >> 4) * 16;
    const int b_off = (wn * 32 + (lane & 15)) * AROWB + (lane >> 4) * 16;

    float acc[2][4][4];
    #pragma unroll
    for (int mf = 0; mf < 2; mf++)
        #pragma unroll
        for (int nf = 0; nf < 4; nf++)
            #pragma unroll
            for (int q = 0; q < 4; q++) acc[mf][nf][q] = 0.0f;

    const int NKT = 2048 / 32;      // 64 chunks

    auto load_stage = [&](int st, int kc) {
        const uint32_t stg = sm0 + st * STG_B;
        const int k0 = kbase + kc * 32;
        // A: 128 rows x 8 segs of 16B
        #pragma unroll
        for (int i = 0; i < 4; i++) {
            int sid = tid + 256 * i;          // 0..1023
            int r = sid >> 3, s = sid & 7;
            cpa16(stg + A_O + r * AROWB + s * 16,
                  Araw + (long long)(m0 + r) * Nn + k0 + s * 4);
        }
        // B: 64 rows x 8 segs of 16B
        #pragma unroll
        for (int i = 0; i < 2; i++) {
            int sid = tid + 256 * i;          // 0..511
            int r = sid >> 3, s = sid & 7;
            cpa16(stg + B_O + r * AROWB + s * 16,
                  g_Bt + (long long)(n0 + r) * Nn + k0 + s * 4);
        }
    };

    load_stage(0, 0); CP_COMMIT();
    load_stage(1, 1); CP_COMMIT();

    for (int kc = 0; kc < NKT; kc++) {
        if (kc == NKT - 1) {
            asm volatile("cp.async.wait_group 0;" ::: "memory");
        } else {
            asm volatile("cp.async.wait_group 1;" ::: "memory");
        }
        __syncthreads();

        const int st = kc & 1;
        const uint32_t stg = sm0 + st * STG_B;

        #pragma unroll
        for (int k8 = 0; k8 < 4; k8++) {
            const uint32_t ko = k8 * 32;

            // A fragments (raw -> register split)
            uint32_t ar0[4], ar1[4];
            LDSM_X4(ar0[0], ar0[1], ar0[2], ar0[3], stg + A_O + a_off + ko);
            LDSM_X4(ar1[0], ar1[1], ar1[2], ar1[3],
                    stg + A_O + a_off + ko + 16 * AROWB);
            uint32_t ah[2][4], al[2][4];
            #pragma unroll
            for (int q = 0; q < 4; q++) {
                tsplit2(ar0[q], ah[0][q], al[0][q]);
                tsplit2(ar1[q], ah[1][q], al[1][q]);
            }

            // B fragments: 2 groups of 16 rows cover the 32-col warp tile
            #pragma unroll
            for (int nbi = 0; nbi < 2; nbi++) {
                uint32_t br[4];
                LDSM_X4(br[0], br[1], br[2], br[3],
                        stg + B_O + b_off + nbi * 16 * AROWB + ko);
                uint32_t bh[4], bl[4];
                #pragma unroll
                for (int q = 0; q < 4; q++) tsplit2(br[q], bh[q], bl[q]);

                const int nf0 = nbi * 2;
                // pass 1: Ah*Bh
                mma1688(acc[0][nf0 + 0], ah[0], bh[0], bh[2]);
                mma1688(acc[0][nf0 + 1], ah[0], bh[1], bh[3]);
                mma1688(acc[1][nf0 + 0], ah[1], bh[0], bh[2]);
                mma1688(acc[1][nf0 + 1], ah[1], bh[1], bh[3]);
                // pass 2: Al*Bh
                mma1688(acc[0][nf0 + 0], al[0], bh[0], bh[2]);
                mma1688(acc[0][nf0 + 1], al[0], bh[1], bh[3]);
                mma1688(acc[1][nf0 + 0], al[1], bh[0], bh[2]);
                mma1688(acc[1][nf0 + 1], al[1], bh[1], bh[3]);
                // pass 3: Ah*Bl
                mma1688(acc[0][nf0 + 0], ah[0], bl[0], bl[2]);
                mma1688(acc[0][nf0 + 1], ah[0], bl[1], bl[3]);
                mma1688(acc[1][nf0 + 0], ah[1], bl[0], bl[2]);
                mma1688(acc[1][nf0 + 1], ah[1], bl[1], bl[3]);
            }
        }
        __syncthreads();

        if (kc + 2 < NKT) { load_stage(st, kc + 2); CP_COMMIT(); }
    }

    // Epilogue: write k-split partials
    float* outp = g_part + (long long)ksz * (Nn * CC);
    const int c2 = t * 2;
    #pragma unroll
    for (int mf = 0; mf < 2; mf++) {
        #pragma unroll
        for (int nf = 0; nf < 4; nf++) {
            const int row = m0 + wm * 32 + mf * 16 + g;
            const int col = n0 + wn * 32 + nf * 8 + c2;
            *(float2*)&outp[(long long)row * CC + col] =
                make_float2(acc[mf][nf][0], acc[mf][nf][1]);
            *(float2*)&outp[(long long)(row + 8) * CC + col] =
                make_float2(acc[mf][nf][2], acc[mf][nf][3]);
        }
    }
}

// ---------------------------------------------------------------------------
// reduce_agg: g_agg = part0 + part1
// ---------------------------------------------------------------------------
__global__ __launch_bounds__(256)
void reduce_agg() {
    const int i4 = blockIdx.x * 256 + threadIdx.x;
    const float4* P = (const float4*)g_part;
    const int S = (Nn * CC) / 4;
    float4 a = P[i4], b = P[S + i4];
    ((float4*)g_agg)[i4] = make_float4(a.x + b.x, a.y + b.y, a.z + b.z, a.w + b.w);
}

// ---------------------------------------------------------------------------
// gates via tensor cores (unchanged from R12, passing).
// ---------------------------------------------------------------------------
#define GA_ROWB 272                       // 64 fp32 + 16B pad
#define GSM_A   0
#define GSM_B   (64 * GA_ROWB)            // 17408
#define GSM_BIAS (GSM_B + 512 * 144)      // 91136
#define GSM_PRE  (GSM_BIAS + 2048)        // 93184
#define GATES_SMEM (GSM_PRE + 4 * 64 * 32 * 4)   // 125952

template <int NGATES, int WOFF>
__device__ __forceinline__ void gates_core(char* dsm, int idx0, int tid,
                                           const float* bias,
                                           float pre_out[2][4][4],
                                           int& wm_o, int& wn_o) {
    const uint32_t sm0 = smem_u32(dsm);
    const int wid  = tid >> 5;
    const int lane = tid & 31;
    const int wm = wid & 1;          // 2 row-groups of 32
    const int wn = wid >> 1;         // gate
    const int t  = lane & 3;
    wm_o = wm; wn_o = wn;

    // ---- A fill: 64 rows x 16 segs of 16B ----
    #pragma unroll
    for (int i = 0; i < 4; i++) {
        int sid = tid + 256 * i;               // 0..1023
        int r = sid >> 4, seg = sid & 15;
        int idx = idx0 + r;
        int b = idx >> 12, n = idx & (Nn - 1);
        int goff = n * CC + ((seg < 8) ? (b * 32 + seg * 4)
                                       : (128 + b * 32 + (seg - 8) * 4));
        cpa16(sm0 + GSM_A + r * GA_ROWB + seg * 16, g_agg + goff);
    }
    // ---- B fill: NGATES*128 cols x 8 segs ----
    const int NB = NGATES * 128 * 8;
    for (int sid = tid; sid < NB; sid += 256) {
        int col = sid >> 3, seg = sid & 7;
        cpa16(sm0 + GSM_B + col * 144 + seg * 16,
              g_Wt + (WOFF + col) * 32 + seg * 4);
    }
    // ---- bias fill ----
    float* smBias = (float*)(dsm + GSM_BIAS);
    for (int colz = tid; colz < NGATES * 128; colz += 256)
        smBias[colz] = bias[WOFF + colz];
    CP_COMMIT(); CP_WAIT0();
    __syncthreads();

    float acc[2][16][4];
    #pragma unroll
    for (int mf = 0; mf < 2; mf++)
        #pragma unroll
        for (int nf = 0; nf < 16; nf++)
            #pragma unroll
            for (int q = 0; q < 4; q++) acc[mf][nf][q] = 0.0f;

    if (wn < NGATES) {
        const uint32_t a_base = sm0 + GSM_A +
            (wm * 32 + (lane & 15)) * GA_ROWB + (lane >> 4) * 16;
        const uint32_t b_base = sm0 + GSM_B +
            (wn * 128 + (lane & 15)) * 144 + (lane >> 4) * 16;

        #pragma unroll
        for (int k8 = 0; k8 < 4; k8++) {
            uint32_t arx0[4], arx1[4], arh0[4], arh1[4];
            LDSM_X4(arx0[0], arx0[1], arx0[2], arx0[3], a_base + k8 * 32);
            LDSM_X4(arx1[0], arx1[1], arx1[2], arx1[3],
                    a_base + k8 * 32 + 16 * GA_ROWB);
            LDSM_X4(arh0[0], arh0[1], arh0[2], arh0[3], a_base + 128 + k8 * 32);
            LDSM_X4(arh1[0], arh1[1], arh1[2], arh1[3],
                    a_base + 128 + k8 * 32 + 16 * GA_ROWB);
            uint32_t axh[2][4], axl[2][4], ahh[2][4], ahl[2][4];
            #pragma unroll
            for (int q = 0; q < 4; q++) {
                tsplit2(arx0[q], axh[0][q], axl[0][q]);
                tsplit2(arx1[q], axh[1][q], axl[1][q]);
                tsplit2(arh0[q], ahh[0][q], ahl[0][q]);
                tsplit2(arh1[q], ahh[1][q], ahl[1][q]);
            }

            #pragma unroll
            for (int nbi = 0; nbi < 8; nbi++) {
                uint32_t br[4];
                LDSM_X4(br[0], br[1], br[2], br[3],
                        b_base + nbi * 16 * 144 + k8 * 32);
                uint32_t bh[4], bl[4];
                #pragma unroll
                for (int q = 0; q < 4; q++) tsplit2(br[q], bh[q], bl[q]);

                const int nf0 = nbi * 2;
                uint32_t (*aH)[4] = (nbi < 4) ? axh : ahh;
                uint32_t (*aL)[4] = (nbi < 4) ? axl : ahl;
                mma1688(acc[0][nf0 + 0], aH[0], bh[0], bh[2]);
                mma1688(acc[0][nf0 + 1], aH[0], bh[1], bh[3]);
                mma1688(acc[1][nf0 + 0], aH[1], bh[0], bh[2]);
                mma1688(acc[1][nf0 + 1], aH[1], bh[1], bh[3]);
                mma1688(acc[0][nf0 + 0], aL[0], bh[0], bh[2]);
                mma1688(acc[0][nf0 + 1], aL[0], bh[1], bh[3]);
                mma1688(acc[1][nf0 + 0], aL[1], bh[0], bh[2]);
                mma1688(acc[1][nf0 + 1], aL[1], bh[1], bh[3]);
                mma1688(acc[0][nf0 + 0], aH[0], bl[0], bl[2]);
                mma1688(acc[0][nf0 + 1], aH[0], bl[1], bl[3]);
                mma1688(acc[1][nf0 + 0], aH[1], bl[0], bl[2]);
                mma1688(acc[1][nf0 + 1], aH[1], bl[1], bl[3]);
            }
        }

        // bias add
        float bv[16][2];
        #pragma unroll
        for (int nf = 0; nf < 16; nf++)
            #pragma unroll
            for (int p = 0; p < 2; p++)
                bv[nf][p] = smBias[wn * 128 + nf * 8 + t * 2 + p];
        #pragma unroll
        for (int mf = 0; mf < 2; mf++)
            #pragma unroll
            for (int nf = 0; nf < 16; nf++)
                #pragma unroll
                for (int q = 0; q < 4; q++)
                    acc[mf][nf][q] += bv[nf][q & 1];

        // GLU per conv + x/h sum
        #pragma unroll
        for (int mf = 0; mf < 2; mf++)
            #pragma unroll
            for (int nf = 0; nf < 4; nf++)
                #pragma unroll
                for (int q = 0; q < 4; q++)
                    pre_out[mf][nf][q] =
                        acc[mf][nf][q]      * sigm(acc[mf][nf + 4][q]) +
                        acc[mf][nf + 8][q]  * sigm(acc[mf][nf + 12][q]);
    }
}

__global__ __launch_bounds__(256, 1)
void gates1_mma(const float* __restrict__ c_in,
                const float* __restrict__ bias,
                float* __restrict__ c_out)
{
    extern __shared__ __align__(16) char dsm[];
    const int tid  = threadIdx.x;
    const int lane = tid & 31;
    const int idx0 = blockIdx.x * 64;

    float pre[2][4][4];
    int wm, wn;
    gates_core<4, 0>(dsm, idx0, tid, bias, pre, wm, wn);

    float* smPre = (float*)(dsm + GSM_PRE);
    {
        const int t = lane & 3, g = lane >> 2;
        #pragma unroll
        for (int mf = 0; mf < 2; mf++)
            #pragma unroll
            for (int nf = 0; nf < 4; nf++)
                #pragma unroll
                for (int q = 0; q < 4; q++) {
                    int row = wm * 32 + mf * 16 + g + ((q >> 1) ? 8 : 0);
                    int j = nf * 8 + t * 2 + (q & 1);
                    smPre[wn * 2048 + row * 32 + j] = pre[mf][nf][q];
                }
    }
    __syncthreads();

    #pragma unroll
    for (int u = 0; u < 8; u++) {
        int cell = tid + 256 * u;     // row*32 + j
        float pf = smPre[cell];
        float pi = smPre[2048 + cell];
        float pc = smPre[2 * 2048 + cell];
        float po = smPre[3 * 2048 + cell];
        float cn = sigm(pf) * c_in[(long long)idx0 * 32 + cell] +
                   sigm(pi) * tanhf(pc);
        c_out[(long long)idx0 * 32 + cell] = cn;
        g_h1[(long long)idx0 * 32 + cell] = sigm(po) * tanhf(cn);
    }
}

__global__ __launch_bounds__(256, 1)
void gates2_mma(const float* __restrict__ m_in,
                const float* __restrict__ bias,
                float* __restrict__ h_out,
                float* __restrict__ m_out)
{
    extern __shared__ __align__(16) char dsm[];
    const int tid  = threadIdx.x;
    const int lane = tid & 31;
    const int idx0 = blockIdx.x * 64;

    float pre[2][4][4];
    int wm, wn;
    gates_core<3, 512>(dsm, idx0, tid, bias, pre, wm, wn);

    float* smPre = (float*)(dsm + GSM_PRE);
    if (wn < 3) {
        const int t = lane & 3, g = lane >> 2;
        #pragma unroll
        for (int mf = 0; mf < 2; mf++)
            #pragma unroll
            for (int nf = 0; nf < 4; nf++)
                #pragma unroll
                for (int q = 0; q < 4; q++) {
                    int row = wm * 32 + mf * 16 + g + ((q >> 1) ? 8 : 0);
                    int j = nf * 8 + t * 2 + (q & 1);
                    smPre[wn * 2048 + row * 32 + j] = pre[mf][nf][q];
                }
    }
    __syncthreads();

    #pragma unroll
    for (int u = 0; u < 8; u++) {
        int cell = tid + 256 * u;
        float i2 = sigm(smPre[cell]);
        float gg = sigm(smPre[2048 + cell]);
        float o2 = sigm(smPre[2 * 2048 + cell]);
        float mn = i2 * m_in[(long long)idx0 * 32 + cell] + (1.0f - i2) * gg;
        m_out[(long long)idx0 * 32 + cell] = mn;
        h_out[(long long)idx0 * 32 + cell] = mn * o2;
    }
}

// ---------------------------------------------------------------------------
// Launch
// ---------------------------------------------------------------------------
extern "C" void kernel_launch(void* const* d_in, const int* in_sizes, int n_in,
                              void* d_out, int out_size) {
    const float* x    = (const float*)d_in[0];
    const float* h    = (const float*)d_in[1];
    const float* c    = (const float*)d_in[2];
    const float* m    = (const float*)d_in[3];
    const float* adj  = (const float*)d_in[4];
    const float* W    = (const float*)d_in[5];
    const float* bias = (const float*)d_in[6];

    float* out   = (float*)d_out;
    float* h_out = out;               // h_new
    float* c_out = out + BNF;         // c_new
    float* m_out = out + 2 * BNF;     // m_new

    cudaFuncSetAttribute(agg_mma, cudaFuncAttributeMaxDynamicSharedMemorySize, AGG_SMEM);
    cudaFuncSetAttribute(gates1_mma, cudaFuncAttributeMaxDynamicSharedMemorySize, GATES_SMEM);
    cudaFuncSetAttribute(gates2_mma, cudaFuncAttributeMaxDynamicSharedMemorySize, GATES_SMEM);

    prep_Wt<<<112, 256>>>(W);

    dim3 agrid(32, 4, 2);   // 256 CTAs -> one wave at 2 CTAs/SM

    // Phase 1
    conv_rhs<<<dim3(64, 8), 256>>>(x, h, 0);
    agg_mma<<<agrid, 256, AGG_SMEM>>>(adj);
    reduce_agg<<<1024, 256>>>();
    gates1_mma<<<256, 256, GATES_SMEM>>>(c, bias, c_out);

    // Phase 2
    conv_rhs<<<dim3(64, 8), 256>>>(nullptr, m, 1);
    agg_mma<<<agrid, 256, AGG_SMEM>>>(adj);
    reduce_agg<<<1024, 256>>>();
    gates2_mma<<<256, 256, GATES_SMEM>>>(m, bias, h_out, m_out);
}

// round 14
// speedup vs baseline: 1.3496x; 1.3496x over previous
#include <cuda_runtime.h>
#include <cstdint>

// Problem constants
#define Nn   4096
#define Bb   4
#define Ff   32
#define NF   (Nn * Ff)        // 131072
#define BNF  (Bb * Nn * Ff)   // 524288
#define CC   256              // 2 sources * B * F columns in aggregation GEMM

// Scratch (no allocs allowed -> device globals)
__device__ float g_agg[Nn * CC];                       // 4 MB
__device__ float g_part[2 * Nn * CC];                  // 8 MB (k-split partials)
__device__ float g_h1[BNF];                            // 2 MB
__device__ __align__(16) float g_Bt[CC * Nn];          // 4 MB rhs tf32-rna, [j][k]
__device__ __align__(16) float g_Wt[14 * 64 * 32];     // W transposed: [conv][j][k]

// ---------------------------------------------------------------------------
// Helpers
// ---------------------------------------------------------------------------
__device__ __forceinline__ uint32_t smem_u32(const void* p) {
    uint32_t a;
    asm("{ .reg .u64 t; cvta.to.shared.u64 t, %1; cvt.u32.u64 %0, t; }"
        : "=r"(a) : "l"(p));
    return a;
}
__device__ __forceinline__ void cpa16(uint32_t s, const void* g) {
    asm volatile("cp.async.cg.shared.global [%0], [%1], 16;" :: "r"(s), "l"(g));
}
#define CP_COMMIT() asm volatile("cp.async.commit_group;" ::: "memory")
#define CP_WAIT0()  asm volatile("cp.async.wait_group 0;" ::: "memory")

#define LDSM_X4(r0, r1, r2, r3, a) \
    asm volatile("ldmatrix.sync.aligned.m8n8.x4.shared.b16 {%0,%1,%2,%3}, [%4];" \
                 : "=r"(r0), "=r"(r1), "=r"(r2), "=r"(r3) : "r"(a))

__device__ __forceinline__ void mma1688(float* c, const uint32_t* a,
                                        uint32_t b0, uint32_t b1) {
    asm volatile(
        "mma.sync.aligned.m16n8k8.row.col.f32.tf32.tf32.f32 "
        "{%0,%1,%2,%3}, {%4,%5,%6,%7}, {%8,%9}, {%0,%1,%2,%3};"
        : "+f"(c[0]), "+f"(c[1]), "+f"(c[2]), "+f"(c[3])
        : "r"(a[0]), "r"(a[1]), "r"(a[2]), "r"(a[3]), "r"(b0), "r"(b1));
}

__device__ __forceinline__ float tf32r(float a) {
    float r;
    asm("cvt.rna.tf32.f32 %0, %1;" : "=f"(r) : "f"(a));
    return r;
}

// trunc-based split (used by gates 3-pass path, proven)
__device__ __forceinline__ void tsplit2(uint32_t r, uint32_t& h, uint32_t& l) {
    h = r & 0xFFFFE000u;
    float lf = __uint_as_float(r) - __uint_as_float(h);
    l = __float_as_uint(lf) & 0xFFFFE000u;
}

// rna-based split for the 2-pass agg path: hi = rna(a) (eps 2^-12),
// lo = (a - hi) masked to a valid tf32 pattern.
__device__ __forceinline__ void tsplit_rna(uint32_t r, uint32_t& h, uint32_t& l) {
    float hf = tf32r(__uint_as_float(r));
    h = __float_as_uint(hf);
    l = __float_as_uint(__uint_as_float(r) - hf) & 0xFFFFE000u;
}

__device__ __forceinline__ float sigm(float x) {
    return 1.0f / (1.0f + __expf(-x));
}

// ---------------------------------------------------------------------------
// prep_Wt: g_Wt[(c*64+j)*32 + k] = W[(c*32+k)*64 + j]
// ---------------------------------------------------------------------------
__global__ __launch_bounds__(256)
void prep_Wt(const float* __restrict__ W) {
    int i = blockIdx.x * 256 + threadIdx.x;    // 0..28671
    if (i < 14 * 64 * 32) {
        int c = i >> 11;
        int rem = i & 2047;
        int j = rem >> 5;
        int k = rem & 31;
        g_Wt[i] = W[(c * 32 + k) * 64 + j];
    }
}

// ---------------------------------------------------------------------------
// conv_rhs: Bt[j][k] = rna-tf32(src[b][k][f]) (j = src*128 + b*32 + f)
// ---------------------------------------------------------------------------
__global__ __launch_bounds__(256)
void conv_rhs(const float* __restrict__ s0in, const float* __restrict__ s1,
              int s0_is_h1) {
    __shared__ float t[64][33];
    const int tid = threadIdx.x;
    const int src = blockIdx.y >> 2;
    const int b   = blockIdx.y & 3;
    const int k0  = blockIdx.x * 64;

    const float* s0 = s0_is_h1 ? (const float*)g_h1 : s0in;
    const float* sp = (src == 0) ? s0 : s1;
    const float* base = sp + b * NF + k0 * Ff;

    #pragma unroll
    for (int i = 0; i < 2; i++) {
        int fi = tid + 256 * i;
        int row = fi >> 3, quad = fi & 7;
        float4 v = *(const float4*)(base + row * Ff + quad * 4);
        t[row][quad * 4 + 0] = v.x; t[row][quad * 4 + 1] = v.y;
        t[row][quad * 4 + 2] = v.z; t[row][quad * 4 + 3] = v.w;
    }
    __syncthreads();

    const int j0 = src * 128 + b * Ff;
    #pragma unroll
    for (int i = 0; i < 2; i++) {
        int oi = tid + 256 * i;
        int f  = oi >> 4;
        int kq = oi & 15;
        float4 v = make_float4(tf32r(t[kq * 4 + 0][f]), tf32r(t[kq * 4 + 1][f]),
                               tf32r(t[kq * 4 + 2][f]), tf32r(t[kq * 4 + 3][f]));
        *(float4*)(g_Bt + (long long)(j0 + f) * Nn + k0 + kq * 4) = v;
    }
}

// ---------------------------------------------------------------------------
// agg_mma: g_part[ks][m][j] = sum_{k in ks range} adj[m][k] * S[k][j]
// tf32 2-pass GEMM: Ah(rna)*Bh + Al*Bh, B pre-rounded to tf32-rna in g_Bt.
// Residual (A*Bl term) calibrated at ~2-5e-4 rel (vs 1e-3 threshold).
// CTA tile 128(M) x 128(N), K-chunk 32, 2-stage cp.async, R12 geometry.
// 8 warps 4m x 2n -> warp tile 32x64. Grid (32 mt, 2 nt, 2 ks) = 128 CTAs.
// ---------------------------------------------------------------------------
#define AROWB 144
#define A_O   0
#define B_O   (128 * AROWB)
#define STG_B (2 * 128 * AROWB)
#define AGG_SMEM (2 * STG_B)

__global__ __launch_bounds__(256, 1)
void agg_mma(const float* __restrict__ Araw) {
    extern __shared__ __align__(16) char dsm[];
    const uint32_t sm0 = smem_u32(dsm);

    const int tid  = threadIdx.x;
    const int wid  = tid >> 5;
    const int lane = tid & 31;
    const int m0   = blockIdx.x * 128;
    const int n0   = blockIdx.y * 128;
    const int ksz  = blockIdx.z;
    const int kbase = ksz * 2048;

    const int wm = wid & 3;
    const int wn = wid >> 2;
    const int t  = lane & 3;
    const int g  = lane >> 2;

    const int a_off = (wm * 32 + (lane & 15)) * AROWB + (lane >> 4) * 16;
    const int b_off = (wn * 64 + (lane & 15)) * AROWB + (lane >> 4) * 16;

    float acc[2][8][4];
    #pragma unroll
    for (int mf = 0; mf < 2; mf++)
        #pragma unroll
        for (int nf = 0; nf < 8; nf++)
            #pragma unroll
            for (int q = 0; q < 4; q++) acc[mf][nf][q] = 0.0f;

    const int NKT = 2048 / 32;

    auto load_stage = [&](int st, int kc) {
        const uint32_t stg = sm0 + st * STG_B;
        const int k0 = kbase + kc * 32;
        #pragma unroll
        for (int i = 0; i < 4; i++) {
            int sid = tid + 256 * i;
            int r = sid >> 3, s = sid & 7;
            uint32_t soff = r * AROWB + s * 16;
            cpa16(stg + A_O + soff, Araw + (long long)(m0 + r) * Nn + k0 + s * 4);
            cpa16(stg + B_O + soff, g_Bt + (long long)(n0 + r) * Nn + k0 + s * 4);
        }
    };

    load_stage(0, 0); CP_COMMIT();
    load_stage(1, 1); CP_COMMIT();

    for (int kc = 0; kc < NKT; kc++) {
        if (kc == NKT - 1) {
            asm volatile("cp.async.wait_group 0;" ::: "memory");
        } else {
            asm volatile("cp.async.wait_group 1;" ::: "memory");
        }
        __syncthreads();

        const int st = kc & 1;
        const uint32_t stg = sm0 + st * STG_B;

        #pragma unroll
        for (int k8 = 0; k8 < 4; k8++) {
            const uint32_t ko = k8 * 32;

            // A fragments: raw -> rna register split
            uint32_t ar0[4], ar1[4];
            LDSM_X4(ar0[0], ar0[1], ar0[2], ar0[3], stg + A_O + a_off + ko);
            LDSM_X4(ar1[0], ar1[1], ar1[2], ar1[3],
                    stg + A_O + a_off + ko + 16 * AROWB);
            uint32_t ah[2][4], al[2][4];
            #pragma unroll
            for (int q = 0; q < 4; q++) {
                tsplit_rna(ar0[q], ah[0][q], al[0][q]);
                tsplit_rna(ar1[q], ah[1][q], al[1][q]);
            }

            // B fragments: already tf32-rna, no split
            #pragma unroll
            for (int nbi = 0; nbi < 4; nbi++) {
                uint32_t br[4];
                LDSM_X4(br[0], br[1], br[2], br[3],
                        stg + B_O + b_off + nbi * 16 * AROWB + ko);

                const int nf0 = nbi * 2;
                // pass 1: Ah*Bh
                mma1688(acc[0][nf0 + 0], ah[0], br[0], br[2]);
                mma1688(acc[0][nf0 + 1], ah[0], br[1], br[3]);
                mma1688(acc[1][nf0 + 0], ah[1], br[0], br[2]);
                mma1688(acc[1][nf0 + 1], ah[1], br[1], br[3]);
                // pass 2: Al*Bh
                mma1688(acc[0][nf0 + 0], al[0], br[0], br[2]);
                mma1688(acc[0][nf0 + 1], al[0], br[1], br[3]);
                mma1688(acc[1][nf0 + 0], al[1], br[0], br[2]);
                mma1688(acc[1][nf0 + 1], al[1], br[1], br[3]);
            }
        }
        __syncthreads();

        if (kc + 2 < NKT) { load_stage(st, kc + 2); CP_COMMIT(); }
    }

    float* outp = g_part + (long long)ksz * (Nn * CC);
    const int c2 = t * 2;
    #pragma unroll
    for (int mf = 0; mf < 2; mf++) {
        #pragma unroll
        for (int nf = 0; nf < 8; nf++) {
            const int row = m0 + wm * 32 + mf * 16 + g;
            const int col = n0 + wn * 64 + nf * 8 + c2;
            *(float2*)&outp[(long long)row * CC + col] =
                make_float2(acc[mf][nf][0], acc[mf][nf][1]);
            *(float2*)&outp[(long long)(row + 8) * CC + col] =
                make_float2(acc[mf][nf][2], acc[mf][nf][3]);
        }
    }
}

// ---------------------------------------------------------------------------
// reduce_agg: g_agg = part0 + part1
// ---------------------------------------------------------------------------
__global__ __launch_bounds__(256)
void reduce_agg() {
    const int i4 = blockIdx.x * 256 + threadIdx.x;
    const float4* P = (const float4*)g_part;
    const int S = (Nn * CC) / 4;
    float4 a = P[i4], b = P[S + i4];
    ((float4*)g_agg)[i4] = make_float4(a.x + b.x, a.y + b.y, a.z + b.z, a.w + b.w);
}

// ---------------------------------------------------------------------------
// gates via tensor cores (unchanged from R12, passing; 3-pass trunc split).
// ---------------------------------------------------------------------------
#define GA_ROWB 272                       // 64 fp32 + 16B pad
#define GSM_A   0
#define GSM_B   (64 * GA_ROWB)            // 17408
#define GSM_BIAS (GSM_B + 512 * 144)      // 91136
#define GSM_PRE  (GSM_BIAS + 2048)        // 93184
#define GATES_SMEM (GSM_PRE + 4 * 64 * 32 * 4)   // 125952

template <int NGATES, int WOFF>
__device__ __forceinline__ void gates_core(char* dsm, int idx0, int tid,
                                           const float* bias,
                                           float pre_out[2][4][4],
                                           int& wm_o, int& wn_o) {
    const uint32_t sm0 = smem_u32(dsm);
    const int wid  = tid >> 5;
    const int lane = tid & 31;
    const int wm = wid & 1;
    const int wn = wid >> 1;
    const int t  = lane & 3;
    wm_o = wm; wn_o = wn;

    #pragma unroll
    for (int i = 0; i < 4; i++) {
        int sid = tid + 256 * i;
        int r = sid >> 4, seg = sid & 15;
        int idx = idx0 + r;
        int b = idx >> 12, n = idx & (Nn - 1);
        int goff = n * CC + ((seg < 8) ? (b * 32 + seg * 4)
                                       : (128 + b * 32 + (seg - 8) * 4));
        cpa16(sm0 + GSM_A + r * GA_ROWB + seg * 16, g_agg + goff);
    }
    const int NB = NGATES * 128 * 8;
    for (int sid = tid; sid < NB; sid += 256) {
        int col = sid >> 3, seg = sid & 7;
        cpa16(sm0 + GSM_B + col * 144 + seg * 16,
              g_Wt + (WOFF + col) * 32 + seg * 4);
    }
    float* smBias = (float*)(dsm + GSM_BIAS);
    for (int colz = tid; colz < NGATES * 128; colz += 256)
        smBias[colz] = bias[WOFF + colz];
    CP_COMMIT(); CP_WAIT0();
    __syncthreads();

    float acc[2][16][4];
    #pragma unroll
    for (int mf = 0; mf < 2; mf++)
        #pragma unroll
        for (int nf = 0; nf < 16; nf++)
            #pragma unroll
            for (int q = 0; q < 4; q++) acc[mf][nf][q] = 0.0f;

    if (wn < NGATES) {
        const uint32_t a_base = sm0 + GSM_A +
            (wm * 32 + (lane & 15)) * GA_ROWB + (lane >> 4) * 16;
        const uint32_t b_base = sm0 + GSM_B +
            (wn * 128 + (lane & 15)) * 144 + (lane >> 4) * 16;

        #pragma unroll
        for (int k8 = 0; k8 < 4; k8++) {
            uint32_t arx0[4], arx1[4], arh0[4], arh1[4];
            LDSM_X4(arx0[0], arx0[1], arx0[2], arx0[3], a_base + k8 * 32);
            LDSM_X4(arx1[0], arx1[1], arx1[2], arx1[3],
                    a_base + k8 * 32 + 16 * GA_ROWB);
            LDSM_X4(arh0[0], arh0[1], arh0[2], arh0[3], a_base + 128 + k8 * 32);
            LDSM_X4(arh1[0], arh1[1], arh1[2], arh1[3],
                    a_base + 128 + k8 * 32 + 16 * GA_ROWB);
            uint32_t axh[2][4], axl[2][4], ahh[2][4], ahl[2][4];
            #pragma unroll
            for (int q = 0; q < 4; q++) {
                tsplit2(arx0[q], axh[0][q], axl[0][q]);
                tsplit2(arx1[q], axh[1][q], axl[1][q]);
                tsplit2(arh0[q], ahh[0][q], ahl[0][q]);
                tsplit2(arh1[q], ahh[1][q], ahl[1][q]);
            }

            #pragma unroll
            for (int nbi = 0; nbi < 8; nbi++) {
                uint32_t br[4];
                LDSM_X4(br[0], br[1], br[2], br[3],
                        b_base + nbi * 16 * 144 + k8 * 32);
                uint32_t bh[4], bl[4];
                #pragma unroll
                for (int q = 0; q < 4; q++) tsplit2(br[q], bh[q], bl[q]);

                const int nf0 = nbi * 2;
                uint32_t (*aH)[4] = (nbi < 4) ? axh : ahh;
                uint32_t (*aL)[4] = (nbi < 4) ? axl : ahl;
                mma1688(acc[0][nf0 + 0], aH[0], bh[0], bh[2]);
                mma1688(acc[0][nf0 + 1], aH[0], bh[1], bh[3]);
                mma1688(acc[1][nf0 + 0], aH[1], bh[0], bh[2]);
                mma1688(acc[1][nf0 + 1], aH[1], bh[1], bh[3]);
                mma1688(acc[0][nf0 + 0], aL[0], bh[0], bh[2]);
                mma1688(acc[0][nf0 + 1], aL[0], bh[1], bh[3]);
                mma1688(acc[1][nf0 + 0], aL[1], bh[0], bh[2]);
                mma1688(acc[1][nf0 + 1], aL[1], bh[1], bh[3]);
                mma1688(acc[0][nf0 + 0], aH[0], bl[0], bl[2]);
                mma1688(acc[0][nf0 + 1], aH[0], bl[1], bl[3]);
                mma1688(acc[1][nf0 + 0], aH[1], bl[0], bl[2]);
                mma1688(acc[1][nf0 + 1], aH[1], bl[1], bl[3]);
            }
        }

        float bv[16][2];
        #pragma unroll
        for (int nf = 0; nf < 16; nf++)
            #pragma unroll
            for (int p = 0; p < 2; p++)
                bv[nf][p] = smBias[wn * 128 + nf * 8 + t * 2 + p];
        #pragma unroll
        for (int mf = 0; mf < 2; mf++)
            #pragma unroll
            for (int nf = 0; nf < 16; nf++)
                #pragma unroll
                for (int q = 0; q < 4; q++)
                    acc[mf][nf][q] += bv[nf][q & 1];

        #pragma unroll
        for (int mf = 0; mf < 2; mf++)
            #pragma unroll
            for (int nf = 0; nf < 4; nf++)
                #pragma unroll
                for (int q = 0; q < 4; q++)
                    pre_out[mf][nf][q] =
                        acc[mf][nf][q]      * sigm(acc[mf][nf + 4][q]) +
                        acc[mf][nf + 8][q]  * sigm(acc[mf][nf + 12][q]);
    }
}

__global__ __launch_bounds__(256, 1)
void gates1_mma(const float* __restrict__ c_in,
                const float* __restrict__ bias,
                float* __restrict__ c_out)
{
    extern __shared__ __align__(16) char dsm[];
    const int tid  = threadIdx.x;
    const int lane = tid & 31;
    const int idx0 = blockIdx.x * 64;

    float pre[2][4][4];
    int wm, wn;
    gates_core<4, 0>(dsm, idx0, tid, bias, pre, wm, wn);

    float* smPre = (float*)(dsm + GSM_PRE);
    {
        const int t = lane & 3, g = lane >> 2;
        #pragma unroll
        for (int mf = 0; mf < 2; mf++)
            #pragma unroll
            for (int nf = 0; nf < 4; nf++)
                #pragma unroll
                for (int q = 0; q < 4; q++) {
                    int row = wm * 32 + mf * 16 + g + ((q >> 1) ? 8 : 0);
                    int j = nf * 8 + t * 2 + (q & 1);
                    smPre[wn * 2048 + row * 32 + j] = pre[mf][nf][q];
                }
    }
    __syncthreads();

    #pragma unroll
    for (int u = 0; u < 8; u++) {
        int cell = tid + 256 * u;
        float pf = smPre[cell];
        float pi = smPre[2048 + cell];
        float pc = smPre[2 * 2048 + cell];
        float po = smPre[3 * 2048 + cell];
        float cn = sigm(pf) * c_in[(long long)idx0 * 32 + cell] +
                   sigm(pi) * tanhf(pc);
        c_out[(long long)idx0 * 32 + cell] = cn;
        g_h1[(long long)idx0 * 32 + cell] = sigm(po) * tanhf(cn);
    }
}

__global__ __launch_bounds__(256, 1)
void gates2_mma(const float* __restrict__ m_in,
                const float* __restrict__ bias,
                float* __restrict__ h_out,
                float* __restrict__ m_out)
{
    extern __shared__ __align__(16) char dsm[];
    const int tid  = threadIdx.x;
    const int lane = tid & 31;
    const int idx0 = blockIdx.x * 64;

    float pre[2][4][4];
    int wm, wn;
    gates_core<3, 512>(dsm, idx0, tid, bias, pre, wm, wn);

    float* smPre = (float*)(dsm + GSM_PRE);
    if (wn < 3) {
        const int t = lane & 3, g = lane >> 2;
        #pragma unroll
        for (int mf = 0; mf < 2; mf++)
            #pragma unroll
            for (int nf = 0; nf < 4; nf++)
                #pragma unroll
                for (int q = 0; q < 4; q++) {
                    int row = wm * 32 + mf * 16 + g + ((q >> 1) ? 8 : 0);
                    int j = nf * 8 + t * 2 + (q & 1);
                    smPre[wn * 2048 + row * 32 + j] = pre[mf][nf][q];
                }
    }
    __syncthreads();

    #pragma unroll
    for (int u = 0; u < 8; u++) {
        int cell = tid + 256 * u;
        float i2 = sigm(smPre[cell]);
        float gg = sigm(smPre[2048 + cell]);
        float o2 = sigm(smPre[2 * 2048 + cell]);
        float mn = i2 * m_in[(long long)idx0 * 32 + cell] + (1.0f - i2) * gg;
        m_out[(long long)idx0 * 32 + cell] = mn;
        h_out[(long long)idx0 * 32 + cell] = mn * o2;
    }
}

// ---------------------------------------------------------------------------
// Launch
// ---------------------------------------------------------------------------
extern "C" void kernel_launch(void* const* d_in, const int* in_sizes, int n_in,
                              void* d_out, int out_size) {
    const float* x    = (const float*)d_in[0];
    const float* h    = (const float*)d_in[1];
    const float* c    = (const float*)d_in[2];
    const float* m    = (const float*)d_in[3];
    const float* adj  = (const float*)d_in[4];
    const float* W    = (const float*)d_in[5];
    const float* bias = (const float*)d_in[6];

    float* out   = (float*)d_out;
    float* h_out = out;               // h_new
    float* c_out = out + BNF;         // c_new
    float* m_out = out + 2 * BNF;     // m_new

    cudaFuncSetAttribute(agg_mma, cudaFuncAttributeMaxDynamicSharedMemorySize, AGG_SMEM);
    cudaFuncSetAttribute(gates1_mma, cudaFuncAttributeMaxDynamicSharedMemorySize, GATES_SMEM);
    cudaFuncSetAttribute(gates2_mma, cudaFuncAttributeMaxDynamicSharedMemorySize, GATES_SMEM);

    prep_Wt<<<112, 256>>>(W);

    dim3 agrid(32, 2, 2);   // R12 geometry

    // Phase 1
    conv_rhs<<<dim3(64, 8), 256>>>(x, h, 0);
    agg_mma<<<agrid, 256, AGG_SMEM>>>(adj);
    reduce_agg<<<1024, 256>>>();
    gates1_mma<<<256, 256, GATES_SMEM>>>(c, bias, c_out);

    // Phase 2
    conv_rhs<<<dim3(64, 8), 256>>>(nullptr, m, 1);
    agg_mma<<<agrid, 256, AGG_SMEM>>>(adj);
    reduce_agg<<<1024, 256>>>();
    gates2_mma<<<256, 256, GATES_SMEM>>>(m, bias, h_out, m_out);
}

// round 15
// speedup vs baseline: 1.9244x; 1.4259x over previous
#include <cuda_runtime.h>
#include <cstdint>

// Problem constants
#define Nn   4096
#define Bb   4
#define Ff   32
#define NF   (Nn * Ff)        // 131072
#define BNF  (Bb * Nn * Ff)   // 524288
#define CC   256              // 2 sources * B * F columns in aggregation GEMM

// Scratch (no allocs allowed -> device globals)
__device__ float g_agg[Nn * CC];                       // 4 MB
__device__ float g_part[2 * Nn * CC];                  // 8 MB (k-split partials)
__device__ float g_h1[BNF];                            // 2 MB
__device__ __align__(16) float g_Bt[CC * Nn];          // 4 MB rhs tf32-rna, [j][k]
__device__ __align__(16) float g_Wt[14 * 64 * 32];     // W^T tf32-rna: [conv][j][k]

// ---------------------------------------------------------------------------
// Helpers
// ---------------------------------------------------------------------------
__device__ __forceinline__ uint32_t smem_u32(const void* p) {
    uint32_t a;
    asm("{ .reg .u64 t; cvta.to.shared.u64 t, %1; cvt.u32.u64 %0, t; }"
        : "=r"(a) : "l"(p));
    return a;
}
__device__ __forceinline__ void cpa16(uint32_t s, const void* g) {
    asm volatile("cp.async.cg.shared.global [%0], [%1], 16;" :: "r"(s), "l"(g));
}
#define CP_COMMIT() asm volatile("cp.async.commit_group;" ::: "memory")
#define CP_WAIT0()  asm volatile("cp.async.wait_group 0;" ::: "memory")

#define LDSM_X4(r0, r1, r2, r3, a) \
    asm volatile("ldmatrix.sync.aligned.m8n8.x4.shared.b16 {%0,%1,%2,%3}, [%4];" \
                 : "=r"(r0), "=r"(r1), "=r"(r2), "=r"(r3) : "r"(a))

__device__ __forceinline__ void mma1688(float* c, const uint32_t* a,
                                        uint32_t b0, uint32_t b1) {
    asm volatile(
        "mma.sync.aligned.m16n8k8.row.col.f32.tf32.tf32.f32 "
        "{%0,%1,%2,%3}, {%4,%5,%6,%7}, {%8,%9}, {%0,%1,%2,%3};"
        : "+f"(c[0]), "+f"(c[1]), "+f"(c[2]), "+f"(c[3])
        : "r"(a[0]), "r"(a[1]), "r"(a[2]), "r"(a[3]), "r"(b0), "r"(b1));
}

__device__ __forceinline__ float tf32r(float a) {
    float r;
    asm("cvt.rna.tf32.f32 %0, %1;" : "=f"(r) : "f"(a));
    return r;
}
__device__ __forceinline__ uint32_t tf32u(uint32_t r) {
    return __float_as_uint(tf32r(__uint_as_float(r)));
}

// Exact 2-term split (trunc hi; hi+lo == a up to lo-mask 2^-24 residue)
__device__ __forceinline__ void tsplit2(uint32_t r, uint32_t& h, uint32_t& l) {
    h = r & 0xFFFFE000u;
    float lf = __uint_as_float(r) - __uint_as_float(h);
    l = __float_as_uint(lf) & 0xFFFFE000u;
}

__device__ __forceinline__ float sigm(float x) {
    return 1.0f / (1.0f + __expf(-x));
}

// ---------------------------------------------------------------------------
// prep_Wt: g_Wt[(c*64+j)*32 + k] = rna-tf32(W[(c*32+k)*64 + j])
// ---------------------------------------------------------------------------
__global__ __launch_bounds__(256)
void prep_Wt(const float* __restrict__ W) {
    int i = blockIdx.x * 256 + threadIdx.x;    // 0..28671
    if (i < 14 * 64 * 32) {
        int c = i >> 11;
        int rem = i & 2047;
        int j = rem >> 5;
        int k = rem & 31;
        g_Wt[i] = tf32r(W[(c * 32 + k) * 64 + j]);
    }
}

// ---------------------------------------------------------------------------
// conv_rhs: Bt[j][k] = rna-tf32(src[b][k][f]) (j = src*128 + b*32 + f)
// ---------------------------------------------------------------------------
__global__ __launch_bounds__(256)
void conv_rhs(const float* __restrict__ s0in, const float* __restrict__ s1,
              int s0_is_h1) {
    __shared__ float t[64][33];
    const int tid = threadIdx.x;
    const int src = blockIdx.y >> 2;
    const int b   = blockIdx.y & 3;
    const int k0  = blockIdx.x * 64;

    const float* s0 = s0_is_h1 ? (const float*)g_h1 : s0in;
    const float* sp = (src == 0) ? s0 : s1;
    const float* base = sp + b * NF + k0 * Ff;

    #pragma unroll
    for (int i = 0; i < 2; i++) {
        int fi = tid + 256 * i;
        int row = fi >> 3, quad = fi & 7;
        float4 v = *(const float4*)(base + row * Ff + quad * 4);
        t[row][quad * 4 + 0] = v.x; t[row][quad * 4 + 1] = v.y;
        t[row][quad * 4 + 2] = v.z; t[row][quad * 4 + 3] = v.w;
    }
    __syncthreads();

    const int j0 = src * 128 + b * Ff;
    #pragma unroll
    for (int i = 0; i < 2; i++) {
        int oi = tid + 256 * i;
        int f  = oi >> 4;
        int kq = oi & 15;
        float4 v = make_float4(tf32r(t[kq * 4 + 0][f]), tf32r(t[kq * 4 + 1][f]),
                               tf32r(t[kq * 4 + 2][f]), tf32r(t[kq * 4 + 3][f]));
        *(float4*)(g_Bt + (long long)(j0 + f) * Nn + k0 + kq * 4) = v;
    }
}

// ---------------------------------------------------------------------------
// agg_mma: g_part[ks][m][j] = sum_{k in ks range} adj[m][k] * S[k][j]
// tf32 1-PASS GEMM: rna(A)*rna(B). Operand-rounding errors accumulate with
// random signs over K=4096 (measured: dropping B-lo cost 1.3e-6 rel) ->
// predicted rel_err ~3e-6, 300x under threshold.
// CTA tile 128(M) x 128(N), K-chunk 32, 2-stage cp.async, R12 geometry.
// 8 warps 4m x 2n -> warp tile 32x64. Grid (32 mt, 2 nt, 2 ks) = 128 CTAs.
// ---------------------------------------------------------------------------
#define AROWB 144
#define A_O   0
#define B_O   (128 * AROWB)
#define STG_B (2 * 128 * AROWB)
#define AGG_SMEM (2 * STG_B)

__global__ __launch_bounds__(256, 1)
void agg_mma(const float* __restrict__ Araw) {
    extern __shared__ __align__(16) char dsm[];
    const uint32_t sm0 = smem_u32(dsm);

    const int tid  = threadIdx.x;
    const int wid  = tid >> 5;
    const int lane = tid & 31;
    const int m0   = blockIdx.x * 128;
    const int n0   = blockIdx.y * 128;
    const int ksz  = blockIdx.z;
    const int kbase = ksz * 2048;

    const int wm = wid & 3;
    const int wn = wid >> 2;
    const int t  = lane & 3;
    const int g  = lane >> 2;

    const int a_off = (wm * 32 + (lane & 15)) * AROWB + (lane >> 4) * 16;
    const int b_off = (wn * 64 + (lane & 15)) * AROWB + (lane >> 4) * 16;

    float acc[2][8][4];
    #pragma unroll
    for (int mf = 0; mf < 2; mf++)
        #pragma unroll
        for (int nf = 0; nf < 8; nf++)
            #pragma unroll
            for (int q = 0; q < 4; q++) acc[mf][nf][q] = 0.0f;

    const int NKT = 2048 / 32;

    auto load_stage = [&](int st, int kc) {
        const uint32_t stg = sm0 + st * STG_B;
        const int k0 = kbase + kc * 32;
        #pragma unroll
        for (int i = 0; i < 4; i++) {
            int sid = tid + 256 * i;
            int r = sid >> 3, s = sid & 7;
            uint32_t soff = r * AROWB + s * 16;
            cpa16(stg + A_O + soff, Araw + (long long)(m0 + r) * Nn + k0 + s * 4);
            cpa16(stg + B_O + soff, g_Bt + (long long)(n0 + r) * Nn + k0 + s * 4);
        }
    };

    load_stage(0, 0); CP_COMMIT();
    load_stage(1, 1); CP_COMMIT();

    for (int kc = 0; kc < NKT; kc++) {
        if (kc == NKT - 1) {
            asm volatile("cp.async.wait_group 0;" ::: "memory");
        } else {
            asm volatile("cp.async.wait_group 1;" ::: "memory");
        }
        __syncthreads();

        const int st = kc & 1;
        const uint32_t stg = sm0 + st * STG_B;

        #pragma unroll
        for (int k8 = 0; k8 < 4; k8++) {
            const uint32_t ko = k8 * 32;

            // A fragments: raw fp32 -> rna tf32 in registers (1 cvt per reg)
            uint32_t ar0[4], ar1[4];
            LDSM_X4(ar0[0], ar0[1], ar0[2], ar0[3], stg + A_O + a_off + ko);
            LDSM_X4(ar1[0], ar1[1], ar1[2], ar1[3],
                    stg + A_O + a_off + ko + 16 * AROWB);
            uint32_t ah[2][4];
            #pragma unroll
            for (int q = 0; q < 4; q++) {
                ah[0][q] = tf32u(ar0[q]);
                ah[1][q] = tf32u(ar1[q]);
            }

            // B fragments: already tf32-rna; single pass
            #pragma unroll
            for (int nbi = 0; nbi < 4; nbi++) {
                uint32_t br[4];
                LDSM_X4(br[0], br[1], br[2], br[3],
                        stg + B_O + b_off + nbi * 16 * AROWB + ko);

                const int nf0 = nbi * 2;
                mma1688(acc[0][nf0 + 0], ah[0], br[0], br[2]);
                mma1688(acc[0][nf0 + 1], ah[0], br[1], br[3]);
                mma1688(acc[1][nf0 + 0], ah[1], br[0], br[2]);
                mma1688(acc[1][nf0 + 1], ah[1], br[1], br[3]);
            }
        }
        __syncthreads();

        if (kc + 2 < NKT) { load_stage(st, kc + 2); CP_COMMIT(); }
    }

    float* outp = g_part + (long long)ksz * (Nn * CC);
    const int c2 = t * 2;
    #pragma unroll
    for (int mf = 0; mf < 2; mf++) {
        #pragma unroll
        for (int nf = 0; nf < 8; nf++) {
            const int row = m0 + wm * 32 + mf * 16 + g;
            const int col = n0 + wn * 64 + nf * 8 + c2;
            *(float2*)&outp[(long long)row * CC + col] =
                make_float2(acc[mf][nf][0], acc[mf][nf][1]);
            *(float2*)&outp[(long long)(row + 8) * CC + col] =
                make_float2(acc[mf][nf][2], acc[mf][nf][3]);
        }
    }
}

// ---------------------------------------------------------------------------
// reduce_agg: g_agg = part0 + part1
// ---------------------------------------------------------------------------
__global__ __launch_bounds__(256)
void reduce_agg() {
    const int i4 = blockIdx.x * 256 + threadIdx.x;
    const float4* P = (const float4*)g_part;
    const int S = (Nn * CC) / 4;
    float4 a = P[i4], b = P[S + i4];
    ((float4*)g_agg)[i4] = make_float4(a.x + b.x, a.y + b.y, a.z + b.z, a.w + b.w);
}

// ---------------------------------------------------------------------------
// gates via tensor cores: 2-pass (A exact trunc-split; W pre-rounded tf32-rna)
// ---------------------------------------------------------------------------
#define GA_ROWB 272                       // 64 fp32 + 16B pad
#define GSM_A   0
#define GSM_B   (64 * GA_ROWB)            // 17408
#define GSM_BIAS (GSM_B + 512 * 144)      // 91136
#define GSM_PRE  (GSM_BIAS + 2048)        // 93184
#define GATES_SMEM (GSM_PRE + 4 * 64 * 32 * 4)   // 125952

template <int NGATES, int WOFF>
__device__ __forceinline__ void gates_core(char* dsm, int idx0, int tid,
                                           const float* bias,
                                           float pre_out[2][4][4],
                                           int& wm_o, int& wn_o) {
    const uint32_t sm0 = smem_u32(dsm);
    const int wid  = tid >> 5;
    const int lane = tid & 31;
    const int wm = wid & 1;
    const int wn = wid >> 1;
    const int t  = lane & 3;
    wm_o = wm; wn_o = wn;

    #pragma unroll
    for (int i = 0; i < 4; i++) {
        int sid = tid + 256 * i;
        int r = sid >> 4, seg = sid & 15;
        int idx = idx0 + r;
        int b = idx >> 12, n = idx & (Nn - 1);
        int goff = n * CC + ((seg < 8) ? (b * 32 + seg * 4)
                                       : (128 + b * 32 + (seg - 8) * 4));
        cpa16(sm0 + GSM_A + r * GA_ROWB + seg * 16, g_agg + goff);
    }
    const int NB = NGATES * 128 * 8;
    for (int sid = tid; sid < NB; sid += 256) {
        int col = sid >> 3, seg = sid & 7;
        cpa16(sm0 + GSM_B + col * 144 + seg * 16,
              g_Wt + (WOFF + col) * 32 + seg * 4);
    }
    float* smBias = (float*)(dsm + GSM_BIAS);
    for (int colz = tid; colz < NGATES * 128; colz += 256)
        smBias[colz] = bias[WOFF + colz];
    CP_COMMIT(); CP_WAIT0();
    __syncthreads();

    float acc[2][16][4];
    #pragma unroll
    for (int mf = 0; mf < 2; mf++)
        #pragma unroll
        for (int nf = 0; nf < 16; nf++)
            #pragma unroll
            for (int q = 0; q < 4; q++) acc[mf][nf][q] = 0.0f;

    if (wn < NGATES) {
        const uint32_t a_base = sm0 + GSM_A +
            (wm * 32 + (lane & 15)) * GA_ROWB + (lane >> 4) * 16;
        const uint32_t b_base = sm0 + GSM_B +
            (wn * 128 + (lane & 15)) * 144 + (lane >> 4) * 16;

        #pragma unroll
        for (int k8 = 0; k8 < 4; k8++) {
            uint32_t arx0[4], arx1[4], arh0[4], arh1[4];
            LDSM_X4(arx0[0], arx0[1], arx0[2], arx0[3], a_base + k8 * 32);
            LDSM_X4(arx1[0], arx1[1], arx1[2], arx1[3],
                    a_base + k8 * 32 + 16 * GA_ROWB);
            LDSM_X4(arh0[0], arh0[1], arh0[2], arh0[3], a_base + 128 + k8 * 32);
            LDSM_X4(arh1[0], arh1[1], arh1[2], arh1[3],
                    a_base + 128 + k8 * 32 + 16 * GA_ROWB);
            uint32_t axh[2][4], axl[2][4], ahh[2][4], ahl[2][4];
            #pragma unroll
            for (int q = 0; q < 4; q++) {
                tsplit2(arx0[q], axh[0][q], axl[0][q]);
                tsplit2(arx1[q], axh[1][q], axl[1][q]);
                tsplit2(arh0[q], ahh[0][q], ahl[0][q]);
                tsplit2(arh1[q], ahh[1][q], ahl[1][q]);
            }

            #pragma unroll
            for (int nbi = 0; nbi < 8; nbi++) {
                uint32_t br[4];
                LDSM_X4(br[0], br[1], br[2], br[3],
                        b_base + nbi * 16 * 144 + k8 * 32);

                const int nf0 = nbi * 2;
                uint32_t (*aH)[4] = (nbi < 4) ? axh : ahh;
                uint32_t (*aL)[4] = (nbi < 4) ? axl : ahl;
                // pass 1: Ahi * W
                mma1688(acc[0][nf0 + 0], aH[0], br[0], br[2]);
                mma1688(acc[0][nf0 + 1], aH[0], br[1], br[3]);
                mma1688(acc[1][nf0 + 0], aH[1], br[0], br[2]);
                mma1688(acc[1][nf0 + 1], aH[1], br[1], br[3]);
                // pass 2: Alo * W
                mma1688(acc[0][nf0 + 0], aL[0], br[0], br[2]);
                mma1688(acc[0][nf0 + 1], aL[0], br[1], br[3]);
                mma1688(acc[1][nf0 + 0], aL[1], br[0], br[2]);
                mma1688(acc[1][nf0 + 1], aL[1], br[1], br[3]);
            }
        }

        float bv[16][2];
        #pragma unroll
        for (int nf = 0; nf < 16; nf++)
            #pragma unroll
            for (int p = 0; p < 2; p++)
                bv[nf][p] = smBias[wn * 128 + nf * 8 + t * 2 + p];
        #pragma unroll
        for (int mf = 0; mf < 2; mf++)
            #pragma unroll
            for (int nf = 0; nf < 16; nf++)
                #pragma unroll
                for (int q = 0; q < 4; q++)
                    acc[mf][nf][q] += bv[nf][q & 1];

        #pragma unroll
        for (int mf = 0; mf < 2; mf++)
            #pragma unroll
            for (int nf = 0; nf < 4; nf++)
                #pragma unroll
                for (int q = 0; q < 4; q++)
                    pre_out[mf][nf][q] =
                        acc[mf][nf][q]      * sigm(acc[mf][nf + 4][q]) +
                        acc[mf][nf + 8][q]  * sigm(acc[mf][nf + 12][q]);
    }
}

__global__ __launch_bounds__(256, 1)
void gates1_mma(const float* __restrict__ c_in,
                const float* __restrict__ bias,
                float* __restrict__ c_out)
{
    extern __shared__ __align__(16) char dsm[];
    const int tid  = threadIdx.x;
    const int lane = tid & 31;
    const int idx0 = blockIdx.x * 64;

    float pre[2][4][4];
    int wm, wn;
    gates_core<4, 0>(dsm, idx0, tid, bias, pre, wm, wn);

    float* smPre = (float*)(dsm + GSM_PRE);
    {
        const int t = lane & 3, g = lane >> 2;
        #pragma unroll
        for (int mf = 0; mf < 2; mf++)
            #pragma unroll
            for (int nf = 0; nf < 4; nf++)
                #pragma unroll
                for (int q = 0; q < 4; q++) {
                    int row = wm * 32 + mf * 16 + g + ((q >> 1) ? 8 : 0);
                    int j = nf * 8 + t * 2 + (q & 1);
                    smPre[wn * 2048 + row * 32 + j] = pre[mf][nf][q];
                }
    }
    __syncthreads();

    #pragma unroll
    for (int u = 0; u < 8; u++) {
        int cell = tid + 256 * u;
        float pf = smPre[cell];
        float pi = smPre[2048 + cell];
        float pc = smPre[2 * 2048 + cell];
        float po = smPre[3 * 2048 + cell];
        float cn = sigm(pf) * c_in[(long long)idx0 * 32 + cell] +
                   sigm(pi) * tanhf(pc);
        c_out[(long long)idx0 * 32 + cell] = cn;
        g_h1[(long long)idx0 * 32 + cell] = sigm(po) * tanhf(cn);
    }
}

__global__ __launch_bounds__(256, 1)
void gates2_mma(const float* __restrict__ m_in,
                const float* __restrict__ bias,
                float* __restrict__ h_out,
                float* __restrict__ m_out)
{
    extern __shared__ __align__(16) char dsm[];
    const int tid  = threadIdx.x;
    const int lane = tid & 31;
    const int idx0 = blockIdx.x * 64;

    float pre[2][4][4];
    int wm, wn;
    gates_core<3, 512>(dsm, idx0, tid, bias, pre, wm, wn);

    float* smPre = (float*)(dsm + GSM_PRE);
    if (wn < 3) {
        const int t = lane & 3, g = lane >> 2;
        #pragma unroll
        for (int mf = 0; mf < 2; mf++)
            #pragma unroll
            for (int nf = 0; nf < 4; nf++)
                #pragma unroll
                for (int q = 0; q < 4; q++) {
                    int row = wm * 32 + mf * 16 + g + ((q >> 1) ? 8 : 0);
                    int j = nf * 8 + t * 2 + (q & 1);
                    smPre[wn * 2048 + row * 32 + j] = pre[mf][nf][q];
                }
    }
    __syncthreads();

    #pragma unroll
    for (int u = 0; u < 8; u++) {
        int cell = tid + 256 * u;
        float i2 = sigm(smPre[cell]);
        float gg = sigm(smPre[2048 + cell]);
        float o2 = sigm(smPre[2 * 2048 + cell]);
        float mn = i2 * m_in[(long long)idx0 * 32 + cell] + (1.0f - i2) * gg;
        m_out[(long long)idx0 * 32 + cell] = mn;
        h_out[(long long)idx0 * 32 + cell] = mn * o2;
    }
}

// ---------------------------------------------------------------------------
// Launch
// ---------------------------------------------------------------------------
extern "C" void kernel_launch(void* const* d_in, const int* in_sizes, int n_in,
                              void* d_out, int out_size) {
    const float* x    = (const float*)d_in[0];
    const float* h    = (const float*)d_in[1];
    const float* c    = (const float*)d_in[2];
    const float* m    = (const float*)d_in[3];
    const float* adj  = (const float*)d_in[4];
    const float* W    = (const float*)d_in[5];
    const float* bias = (const float*)d_in[6];

    float* out   = (float*)d_out;
    float* h_out = out;               // h_new
    float* c_out = out + BNF;         // c_new
    float* m_out = out + 2 * BNF;     // m_new

    cudaFuncSetAttribute(agg_mma, cudaFuncAttributeMaxDynamicSharedMemorySize, AGG_SMEM);
    cudaFuncSetAttribute(gates1_mma, cudaFuncAttributeMaxDynamicSharedMemorySize, GATES_SMEM);
    cudaFuncSetAttribute(gates2_mma, cudaFuncAttributeMaxDynamicSharedMemorySize, GATES_SMEM);

    prep_Wt<<<112, 256>>>(W);

    dim3 agrid(32, 2, 2);   // R12 geometry

    // Phase 1
    conv_rhs<<<dim3(64, 8), 256>>>(x, h, 0);
    agg_mma<<<agrid, 256, AGG_SMEM>>>(adj);
    reduce_agg<<<1024, 256>>>();
    gates1_mma<<<256, 256, GATES_SMEM>>>(c, bias, c_out);

    // Phase 2
    conv_rhs<<<dim3(64, 8), 256>>>(nullptr, m, 1);
    agg_mma<<<agrid, 256, AGG_SMEM>>>(adj);
    reduce_agg<<<1024, 256>>>();
    gates2_mma<<<256, 256, GATES_SMEM>>>(m, bias, h_out, m_out);
}

// round 16
// speedup vs baseline: 1.9744x; 1.0260x over previous
#include <cuda_runtime.h>
#include <cstdint>

// Problem constants
#define Nn   4096
#define Bb   4
#define Ff   32
#define NF   (Nn * Ff)        // 131072
#define BNF  (Bb * Nn * Ff)   // 524288
#define CC   256              // 2 sources * B * F columns in aggregation GEMM

// Scratch (no allocs allowed -> device globals)
__device__ float g_agg[Nn * CC];                       // 4 MB
__device__ float g_part[2 * Nn * CC];                  // 8 MB (k-split partials)
__device__ float g_h1[BNF];                            // 2 MB
__device__ __align__(16) float g_Bt[CC * Nn];          // 4 MB rhs tf32-rna, [j][k]
__device__ __align__(16) float g_Wt[14 * 64 * 32];     // W^T tf32-rna: [conv][j][k]

// ---------------------------------------------------------------------------
// Helpers
// ---------------------------------------------------------------------------
__device__ __forceinline__ uint32_t smem_u32(const void* p) {
    uint32_t a;
    asm("{ .reg .u64 t; cvta.to.shared.u64 t, %1; cvt.u32.u64 %0, t; }"
        : "=r"(a) : "l"(p));
    return a;
}
__device__ __forceinline__ void cpa16(uint32_t s, const void* g) {
    asm volatile("cp.async.cg.shared.global [%0], [%1], 16;" :: "r"(s), "l"(g));
}
#define CP_COMMIT() asm volatile("cp.async.commit_group;" ::: "memory")
#define CP_WAIT0()  asm volatile("cp.async.wait_group 0;" ::: "memory")

#define LDSM_X4(r0, r1, r2, r3, a) \
    asm volatile("ldmatrix.sync.aligned.m8n8.x4.shared.b16 {%0,%1,%2,%3}, [%4];" \
                 : "=r"(r0), "=r"(r1), "=r"(r2), "=r"(r3) : "r"(a))

__device__ __forceinline__ void mma1688(float* c, const uint32_t* a,
                                        uint32_t b0, uint32_t b1) {
    asm volatile(
        "mma.sync.aligned.m16n8k8.row.col.f32.tf32.tf32.f32 "
        "{%0,%1,%2,%3}, {%4,%5,%6,%7}, {%8,%9}, {%0,%1,%2,%3};"
        : "+f"(c[0]), "+f"(c[1]), "+f"(c[2]), "+f"(c[3])
        : "r"(a[0]), "r"(a[1]), "r"(a[2]), "r"(a[3]), "r"(b0), "r"(b1));
}

__device__ __forceinline__ float tf32r(float a) {
    float r;
    asm("cvt.rna.tf32.f32 %0, %1;" : "=f"(r) : "f"(a));
    return r;
}
__device__ __forceinline__ uint32_t tf32u(uint32_t r) {
    return __float_as_uint(tf32r(__uint_as_float(r)));
}

__device__ __forceinline__ float sigm(float x) {
    return 1.0f / (1.0f + __expf(-x));
}

// ---------------------------------------------------------------------------
// prep_Wt: g_Wt[(c*64+j)*32 + k] = rna-tf32(W[(c*32+k)*64 + j])
// ---------------------------------------------------------------------------
__global__ __launch_bounds__(256)
void prep_Wt(const float* __restrict__ W) {
    int i = blockIdx.x * 256 + threadIdx.x;    // 0..28671
    if (i < 14 * 64 * 32) {
        int c = i >> 11;
        int rem = i & 2047;
        int j = rem >> 5;
        int k = rem & 31;
        g_Wt[i] = tf32r(W[(c * 32 + k) * 64 + j]);
    }
}

// ---------------------------------------------------------------------------
// conv_rhs: Bt[j][k] = rna-tf32(src[b][k][f]) (j = src*128 + b*32 + f)
// ---------------------------------------------------------------------------
__global__ __launch_bounds__(256)
void conv_rhs(const float* __restrict__ s0in, const float* __restrict__ s1,
              int s0_is_h1) {
    __shared__ float t[64][33];
    const int tid = threadIdx.x;
    const int src = blockIdx.y >> 2;
    const int b   = blockIdx.y & 3;
    const int k0  = blockIdx.x * 64;

    const float* s0 = s0_is_h1 ? (const float*)g_h1 : s0in;
    const float* sp = (src == 0) ? s0 : s1;
    const float* base = sp + b * NF + k0 * Ff;

    #pragma unroll
    for (int i = 0; i < 2; i++) {
        int fi = tid + 256 * i;
        int row = fi >> 3, quad = fi & 7;
        float4 v = *(const float4*)(base + row * Ff + quad * 4);
        t[row][quad * 4 + 0] = v.x; t[row][quad * 4 + 1] = v.y;
        t[row][quad * 4 + 2] = v.z; t[row][quad * 4 + 3] = v.w;
    }
    __syncthreads();

    const int j0 = src * 128 + b * Ff;
    #pragma unroll
    for (int i = 0; i < 2; i++) {
        int oi = tid + 256 * i;
        int f  = oi >> 4;
        int kq = oi & 15;
        float4 v = make_float4(tf32r(t[kq * 4 + 0][f]), tf32r(t[kq * 4 + 1][f]),
                               tf32r(t[kq * 4 + 2][f]), tf32r(t[kq * 4 + 3][f]));
        *(float4*)(g_Bt + (long long)(j0 + f) * Nn + k0 + kq * 4) = v;
    }
}

// ---------------------------------------------------------------------------
// agg_mma: g_part[ks][m][j] = sum_{k in ks range} adj[m][k] * S[k][j]
// tf32 1-pass GEMM, 3-stage cp.async ring, ONE __syncthreads per chunk.
// Ring safety: the load issued at iter kc targets slot (kc+2)%3, which was
// consumed at iter kc-1; the top-of-loop barrier at iter kc fences all warps
// past compute(kc-1) before the load issues.
// CTA tile 128(M) x 128(N), K-chunk 32. Grid (32 mt, 2 nt, 2 ks) = 128 CTAs.
// ---------------------------------------------------------------------------
#define AROWB 144
#define A_O   0
#define B_O   (128 * AROWB)
#define STG_B (2 * 128 * AROWB)      // 36864
#define AGG_SMEM (3 * STG_B)         // 110592

__global__ __launch_bounds__(256, 1)
void agg_mma(const float* __restrict__ Araw) {
    extern __shared__ __align__(16) char dsm[];
    const uint32_t sm0 = smem_u32(dsm);

    const int tid  = threadIdx.x;
    const int wid  = tid >> 5;
    const int lane = tid & 31;
    const int m0   = blockIdx.x * 128;
    const int n0   = blockIdx.y * 128;
    const int ksz  = blockIdx.z;
    const int kbase = ksz * 2048;

    const int wm = wid & 3;
    const int wn = wid >> 2;
    const int t  = lane & 3;
    const int g  = lane >> 2;

    const int a_off = (wm * 32 + (lane & 15)) * AROWB + (lane >> 4) * 16;
    const int b_off = (wn * 64 + (lane & 15)) * AROWB + (lane >> 4) * 16;

    float acc[2][8][4];
    #pragma unroll
    for (int mf = 0; mf < 2; mf++)
        #pragma unroll
        for (int nf = 0; nf < 8; nf++)
            #pragma unroll
            for (int q = 0; q < 4; q++) acc[mf][nf][q] = 0.0f;

    const int NKT = 2048 / 32;       // 64 chunks

    auto load_stage = [&](int slot, int kc) {
        const uint32_t stg = sm0 + slot * STG_B;
        const int k0 = kbase + kc * 32;
        #pragma unroll
        for (int i = 0; i < 4; i++) {
            int sid = tid + 256 * i;
            int r = sid >> 3, s = sid & 7;
            uint32_t soff = r * AROWB + s * 16;
            cpa16(stg + A_O + soff, Araw + (long long)(m0 + r) * Nn + k0 + s * 4);
            cpa16(stg + B_O + soff, g_Bt + (long long)(n0 + r) * Nn + k0 + s * 4);
        }
    };

    load_stage(0, 0); CP_COMMIT();
    load_stage(1, 1); CP_COMMIT();

    int slot = 0;
    for (int kc = 0; kc < NKT; kc++) {
        if (kc == NKT - 1) {
            asm volatile("cp.async.wait_group 0;" ::: "memory");
        } else {
            asm volatile("cp.async.wait_group 1;" ::: "memory");
        }
        __syncthreads();

        // issue next loads BEFORE compute (overlap); slot safety per header
        if (kc + 2 < NKT) {
            int ns = slot + 2; if (ns >= 3) ns -= 3;
            load_stage(ns, kc + 2);
            CP_COMMIT();
        }

        const uint32_t stg = sm0 + slot * STG_B;

        #pragma unroll
        for (int k8 = 0; k8 < 4; k8++) {
            const uint32_t ko = k8 * 32;

            uint32_t ar0[4], ar1[4];
            LDSM_X4(ar0[0], ar0[1], ar0[2], ar0[3], stg + A_O + a_off + ko);
            LDSM_X4(ar1[0], ar1[1], ar1[2], ar1[3],
                    stg + A_O + a_off + ko + 16 * AROWB);
            uint32_t ah[2][4];
            #pragma unroll
            for (int q = 0; q < 4; q++) {
                ah[0][q] = tf32u(ar0[q]);
                ah[1][q] = tf32u(ar1[q]);
            }

            #pragma unroll
            for (int nbi = 0; nbi < 4; nbi++) {
                uint32_t br[4];
                LDSM_X4(br[0], br[1], br[2], br[3],
                        stg + B_O + b_off + nbi * 16 * AROWB + ko);

                const int nf0 = nbi * 2;
                mma1688(acc[0][nf0 + 0], ah[0], br[0], br[2]);
                mma1688(acc[0][nf0 + 1], ah[0], br[1], br[3]);
                mma1688(acc[1][nf0 + 0], ah[1], br[0], br[2]);
                mma1688(acc[1][nf0 + 1], ah[1], br[1], br[3]);
            }
        }

        if (++slot == 3) slot = 0;
    }

    float* outp = g_part + (long long)ksz * (Nn * CC);
    const int c2 = t * 2;
    #pragma unroll
    for (int mf = 0; mf < 2; mf++) {
        #pragma unroll
        for (int nf = 0; nf < 8; nf++) {
            const int row = m0 + wm * 32 + mf * 16 + g;
            const int col = n0 + wn * 64 + nf * 8 + c2;
            *(float2*)&outp[(long long)row * CC + col] =
                make_float2(acc[mf][nf][0], acc[mf][nf][1]);
            *(float2*)&outp[(long long)(row + 8) * CC + col] =
                make_float2(acc[mf][nf][2], acc[mf][nf][3]);
        }
    }
}

// ---------------------------------------------------------------------------
// reduce_agg: g_agg = part0 + part1
// ---------------------------------------------------------------------------
__global__ __launch_bounds__(256)
void reduce_agg() {
    const int i4 = blockIdx.x * 256 + threadIdx.x;
    const float4* P = (const float4*)g_part;
    const int S = (Nn * CC) / 4;
    float4 a = P[i4], b = P[S + i4];
    ((float4*)g_agg)[i4] = make_float4(a.x + b.x, a.y + b.y, a.z + b.z, a.w + b.w);
}

// ---------------------------------------------------------------------------
// gates via tensor cores: 1-pass (A rna-rounded in regs; W pre-rounded rna)
// ---------------------------------------------------------------------------
#define GA_ROWB 272                       // 64 fp32 + 16B pad
#define GSM_A   0
#define GSM_B   (64 * GA_ROWB)            // 17408
#define GSM_BIAS (GSM_B + 512 * 144)      // 91136
#define GSM_PRE  (GSM_BIAS + 2048)        // 93184
#define GATES_SMEM (GSM_PRE + 4 * 64 * 32 * 4)   // 125952

template <int NGATES, int WOFF>
__device__ __forceinline__ void gates_core(char* dsm, int idx0, int tid,
                                           const float* bias,
                                           float pre_out[2][4][4],
                                           int& wm_o, int& wn_o) {
    const uint32_t sm0 = smem_u32(dsm);
    const int wid  = tid >> 5;
    const int lane = tid & 31;
    const int wm = wid & 1;
    const int wn = wid >> 1;
    const int t  = lane & 3;
    wm_o = wm; wn_o = wn;

    #pragma unroll
    for (int i = 0; i < 4; i++) {
        int sid = tid + 256 * i;
        int r = sid >> 4, seg = sid & 15;
        int idx = idx0 + r;
        int b = idx >> 12, n = idx & (Nn - 1);
        int goff = n * CC + ((seg < 8) ? (b * 32 + seg * 4)
                                       : (128 + b * 32 + (seg - 8) * 4));
        cpa16(sm0 + GSM_A + r * GA_ROWB + seg * 16, g_agg + goff);
    }
    const int NB = NGATES * 128 * 8;
    for (int sid = tid; sid < NB; sid += 256) {
        int col = sid >> 3, seg = sid & 7;
        cpa16(sm0 + GSM_B + col * 144 + seg * 16,
              g_Wt + (WOFF + col) * 32 + seg * 4);
    }
    float* smBias = (float*)(dsm + GSM_BIAS);
    for (int colz = tid; colz < NGATES * 128; colz += 256)
        smBias[colz] = bias[WOFF + colz];
    CP_COMMIT(); CP_WAIT0();
    __syncthreads();

    float acc[2][16][4];
    #pragma unroll
    for (int mf = 0; mf < 2; mf++)
        #pragma unroll
        for (int nf = 0; nf < 16; nf++)
            #pragma unroll
            for (int q = 0; q < 4; q++) acc[mf][nf][q] = 0.0f;

    if (wn < NGATES) {
        const uint32_t a_base = sm0 + GSM_A +
            (wm * 32 + (lane & 15)) * GA_ROWB + (lane >> 4) * 16;
        const uint32_t b_base = sm0 + GSM_B +
            (wn * 128 + (lane & 15)) * 144 + (lane >> 4) * 16;

        #pragma unroll
        for (int k8 = 0; k8 < 4; k8++) {
            uint32_t arx0[4], arx1[4], arh0[4], arh1[4];
            LDSM_X4(arx0[0], arx0[1], arx0[2], arx0[3], a_base + k8 * 32);
            LDSM_X4(arx1[0], arx1[1], arx1[2], arx1[3],
                    a_base + k8 * 32 + 16 * GA_ROWB);
            LDSM_X4(arh0[0], arh0[1], arh0[2], arh0[3], a_base + 128 + k8 * 32);
            LDSM_X4(arh1[0], arh1[1], arh1[2], arh1[3],
                    a_base + 128 + k8 * 32 + 16 * GA_ROWB);
            uint32_t ax[2][4], ahh[2][4];
            #pragma unroll
            for (int q = 0; q < 4; q++) {
                ax[0][q]  = tf32u(arx0[q]);
                ax[1][q]  = tf32u(arx1[q]);
                ahh[0][q] = tf32u(arh0[q]);
                ahh[1][q] = tf32u(arh1[q]);
            }

            #pragma unroll
            for (int nbi = 0; nbi < 8; nbi++) {
                uint32_t br[4];
                LDSM_X4(br[0], br[1], br[2], br[3],
                        b_base + nbi * 16 * 144 + k8 * 32);

                const int nf0 = nbi * 2;
                uint32_t (*aH)[4] = (nbi < 4) ? ax : ahh;
                mma1688(acc[0][nf0 + 0], aH[0], br[0], br[2]);
                mma1688(acc[0][nf0 + 1], aH[0], br[1], br[3]);
                mma1688(acc[1][nf0 + 0], aH[1], br[0], br[2]);
                mma1688(acc[1][nf0 + 1], aH[1], br[1], br[3]);
            }
        }

        float bv[16][2];
        #pragma unroll
        for (int nf = 0; nf < 16; nf++)
            #pragma unroll
            for (int p = 0; p < 2; p++)
                bv[nf][p] = smBias[wn * 128 + nf * 8 + t * 2 + p];
        #pragma unroll
        for (int mf = 0; mf < 2; mf++)
            #pragma unroll
            for (int nf = 0; nf < 16; nf++)
                #pragma unroll
                for (int q = 0; q < 4; q++)
                    acc[mf][nf][q] += bv[nf][q & 1];

        #pragma unroll
        for (int mf = 0; mf < 2; mf++)
            #pragma unroll
            for (int nf = 0; nf < 4; nf++)
                #pragma unroll
                for (int q = 0; q < 4; q++)
                    pre_out[mf][nf][q] =
                        acc[mf][nf][q]      * sigm(acc[mf][nf + 4][q]) +
                        acc[mf][nf + 8][q]  * sigm(acc[mf][nf + 12][q]);
    }
}

__global__ __launch_bounds__(256, 1)
void gates1_mma(const float* __restrict__ c_in,
                const float* __restrict__ bias,
                float* __restrict__ c_out)
{
    extern __shared__ __align__(16) char dsm[];
    const int tid  = threadIdx.x;
    const int lane = tid & 31;
    const int idx0 = blockIdx.x * 64;

    float pre[2][4][4];
    int wm, wn;
    gates_core<4, 0>(dsm, idx0, tid, bias, pre, wm, wn);

    float* smPre = (float*)(dsm + GSM_PRE);
    {
        const int t = lane & 3, g = lane >> 2;
        #pragma unroll
        for (int mf = 0; mf < 2; mf++)
            #pragma unroll
            for (int nf = 0; nf < 4; nf++)
                #pragma unroll
                for (int q = 0; q < 4; q++) {
                    int row = wm * 32 + mf * 16 + g + ((q >> 1) ? 8 : 0);
                    int j = nf * 8 + t * 2 + (q & 1);
                    smPre[wn * 2048 + row * 32 + j] = pre[mf][nf][q];
                }
    }
    __syncthreads();

    #pragma unroll
    for (int u = 0; u < 8; u++) {
        int cell = tid + 256 * u;
        float pf = smPre[cell];
        float pi = smPre[2048 + cell];
        float pc = smPre[2 * 2048 + cell];
        float po = smPre[3 * 2048 + cell];
        float cn = sigm(pf) * c_in[(long long)idx0 * 32 + cell] +
                   sigm(pi) * tanhf(pc);
        c_out[(long long)idx0 * 32 + cell] = cn;
        g_h1[(long long)idx0 * 32 + cell] = sigm(po) * tanhf(cn);
    }
}

__global__ __launch_bounds__(256, 1)
void gates2_mma(const float* __restrict__ m_in,
                const float* __restrict__ bias,
                float* __restrict__ h_out,
                float* __restrict__ m_out)
{
    extern __shared__ __align__(16) char dsm[];
    const int tid  = threadIdx.x;
    const int lane = tid & 31;
    const int idx0 = blockIdx.x * 64;

    float pre[2][4][4];
    int wm, wn;
    gates_core<3, 512>(dsm, idx0, tid, bias, pre, wm, wn);

    float* smPre = (float*)(dsm + GSM_PRE);
    if (wn < 3) {
        const int t = lane & 3, g = lane >> 2;
        #pragma unroll
        for (int mf = 0; mf < 2; mf++)
            #pragma unroll
            for (int nf = 0; nf < 4; nf++)
                #pragma unroll
                for (int q = 0; q < 4; q++) {
                    int row = wm * 32 + mf * 16 + g + ((q >> 1) ? 8 : 0);
                    int j = nf * 8 + t * 2 + (q & 1);
                    smPre[wn * 2048 + row * 32 + j] = pre[mf][nf][q];
                }
    }
    __syncthreads();

    #pragma unroll
    for (int u = 0; u < 8; u++) {
        int cell = tid + 256 * u;
        float i2 = sigm(smPre[cell]);
        float gg = sigm(smPre[2048 + cell]);
        float o2 = sigm(smPre[2 * 2048 + cell]);
        float mn = i2 * m_in[(long long)idx0 * 32 + cell] + (1.0f - i2) * gg;
        m_out[(long long)idx0 * 32 + cell] = mn;
        h_out[(long long)idx0 * 32 + cell] = mn * o2;
    }
}

// ---------------------------------------------------------------------------
// Launch
// ---------------------------------------------------------------------------
extern "C" void kernel_launch(void* const* d_in, const int* in_sizes, int n_in,
                              void* d_out, int out_size) {
    const float* x    = (const float*)d_in[0];
    const float* h    = (const float*)d_in[1];
    const float* c    = (const float*)d_in[2];
    const float* m    = (const float*)d_in[3];
    const float* adj  = (const float*)d_in[4];
    const float* W    = (const float*)d_in[5];
    const float* bias = (const float*)d_in[6];

    float* out   = (float*)d_out;
    float* h_out = out;               // h_new
    float* c_out = out + BNF;         // c_new
    float* m_out = out + 2 * BNF;     // m_new

    cudaFuncSetAttribute(agg_mma, cudaFuncAttributeMaxDynamicSharedMemorySize, AGG_SMEM);
    cudaFuncSetAttribute(gates1_mma, cudaFuncAttributeMaxDynamicSharedMemorySize, GATES_SMEM);
    cudaFuncSetAttribute(gates2_mma, cudaFuncAttributeMaxDynamicSharedMemorySize, GATES_SMEM);

    prep_Wt<<<112, 256>>>(W);

    dim3 agrid(32, 2, 2);

    // Phase 1
    conv_rhs<<<dim3(64, 8), 256>>>(x, h, 0);
    agg_mma<<<agrid, 256, AGG_SMEM>>>(adj);
    reduce_agg<<<1024, 256>>>();
    gates1_mma<<<256, 256, GATES_SMEM>>>(c, bias, c_out);

    // Phase 2
    conv_rhs<<<dim3(64, 8), 256>>>(nullptr, m, 1);
    agg_mma<<<agrid, 256, AGG_SMEM>>>(adj);
    reduce_agg<<<1024, 256>>>();
    gates2_mma<<<256, 256, GATES_SMEM>>>(m, bias, h_out, m_out);
}

// round 17
// speedup vs baseline: 2.0701x; 1.0485x over previous
#include <cuda_runtime.h>
#include <cstdint>

// Problem constants
#define Nn   4096
#define Bb   4
#define Ff   32
#define NF   (Nn * Ff)        // 131072
#define BNF  (Bb * Nn * Ff)   // 524288
#define CC   256              // 2 sources * B * F columns in aggregation GEMM
#define KSPLIT 4

// Scratch (no allocs allowed -> device globals)
__device__ float g_agg[Nn * CC];                       // 4 MB
__device__ float g_part[KSPLIT * Nn * CC];             // 16 MB (k-split partials)
__device__ float g_h1[BNF];                            // 2 MB
__device__ __align__(16) float g_Bt[CC * Nn];          // 4 MB rhs tf32-rna, [j][k]
__device__ __align__(16) float g_Wt[14 * 64 * 32];     // W^T tf32-rna: [conv][j][k]

// ---------------------------------------------------------------------------
// Helpers
// ---------------------------------------------------------------------------
__device__ __forceinline__ uint32_t smem_u32(const void* p) {
    uint32_t a;
    asm("{ .reg .u64 t; cvta.to.shared.u64 t, %1; cvt.u32.u64 %0, t; }"
        : "=r"(a) : "l"(p));
    return a;
}
__device__ __forceinline__ void cpa16(uint32_t s, const void* g) {
    asm volatile("cp.async.cg.shared.global [%0], [%1], 16;" :: "r"(s), "l"(g));
}
#define CP_COMMIT() asm volatile("cp.async.commit_group;" ::: "memory")
#define CP_WAIT0()  asm volatile("cp.async.wait_group 0;" ::: "memory")

#define LDSM_X4(r0, r1, r2, r3, a) \
    asm volatile("ldmatrix.sync.aligned.m8n8.x4.shared.b16 {%0,%1,%2,%3}, [%4];" \
                 : "=r"(r0), "=r"(r1), "=r"(r2), "=r"(r3) : "r"(a))

__device__ __forceinline__ void mma1688(float* c, const uint32_t* a,
                                        uint32_t b0, uint32_t b1) {
    asm volatile(
        "mma.sync.aligned.m16n8k8.row.col.f32.tf32.tf32.f32 "
        "{%0,%1,%2,%3}, {%4,%5,%6,%7}, {%8,%9}, {%0,%1,%2,%3};"
        : "+f"(c[0]), "+f"(c[1]), "+f"(c[2]), "+f"(c[3])
        : "r"(a[0]), "r"(a[1]), "r"(a[2]), "r"(a[3]), "r"(b0), "r"(b1));
}

__device__ __forceinline__ float tf32r(float a) {
    float r;
    asm("cvt.rna.tf32.f32 %0, %1;" : "=f"(r) : "f"(a));
    return r;
}
__device__ __forceinline__ uint32_t tf32u(uint32_t r) {
    return __float_as_uint(tf32r(__uint_as_float(r)));
}

__device__ __forceinline__ float sigm(float x) {
    return 1.0f / (1.0f + __expf(-x));
}

// ---------------------------------------------------------------------------
// prep_Wt: g_Wt[(c*64+j)*32 + k] = rna-tf32(W[(c*32+k)*64 + j])
// ---------------------------------------------------------------------------
__global__ __launch_bounds__(256)
void prep_Wt(const float* __restrict__ W) {
    int i = blockIdx.x * 256 + threadIdx.x;    // 0..28671
    if (i < 14 * 64 * 32) {
        int c = i >> 11;
        int rem = i & 2047;
        int j = rem >> 5;
        int k = rem & 31;
        g_Wt[i] = tf32r(W[(c * 32 + k) * 64 + j]);
    }
}

// ---------------------------------------------------------------------------
// conv_rhs: Bt[j][k] = rna-tf32(src[b][k][f]) (j = src*128 + b*32 + f)
// ---------------------------------------------------------------------------
__global__ __launch_bounds__(256)
void conv_rhs(const float* __restrict__ s0in, const float* __restrict__ s1,
              int s0_is_h1) {
    __shared__ float t[64][33];
    const int tid = threadIdx.x;
    const int src = blockIdx.y >> 2;
    const int b   = blockIdx.y & 3;
    const int k0  = blockIdx.x * 64;

    const float* s0 = s0_is_h1 ? (const float*)g_h1 : s0in;
    const float* sp = (src == 0) ? s0 : s1;
    const float* base = sp + b * NF + k0 * Ff;

    #pragma unroll
    for (int i = 0; i < 2; i++) {
        int fi = tid + 256 * i;
        int row = fi >> 3, quad = fi & 7;
        float4 v = *(const float4*)(base + row * Ff + quad * 4);
        t[row][quad * 4 + 0] = v.x; t[row][quad * 4 + 1] = v.y;
        t[row][quad * 4 + 2] = v.z; t[row][quad * 4 + 3] = v.w;
    }
    __syncthreads();

    const int j0 = src * 128 + b * Ff;
    #pragma unroll
    for (int i = 0; i < 2; i++) {
        int oi = tid + 256 * i;
        int f  = oi >> 4;
        int kq = oi & 15;
        float4 v = make_float4(tf32r(t[kq * 4 + 0][f]), tf32r(t[kq * 4 + 1][f]),
                               tf32r(t[kq * 4 + 2][f]), tf32r(t[kq * 4 + 3][f]));
        *(float4*)(g_Bt + (long long)(j0 + f) * Nn + k0 + kq * 4) = v;
    }
}

// ---------------------------------------------------------------------------
// agg_mma: g_part[ks][m][j] = sum_{k in ks range} adj[m][k] * S[k][j]
// tf32 1-pass GEMM, 3-stage cp.async ring, one barrier per chunk.
// 2 CTAs/SM (smem 110.6KB x2 = 221KB < 228KB; regs capped by launch_bounds)
// so the ~450 non-HMMA issue-cycles/chunk hide under the co-CTA's HMMAs.
// CTA tile 128(M) x 128(N), K-chunk 32, per-CTA K=1024.
// Grid (32 mt, 2 nt, 4 ks) = 256 CTAs = one wave at 2/SM.
// ---------------------------------------------------------------------------
#define AROWB 144
#define A_O   0
#define B_O   (128 * AROWB)
#define STG_B (2 * 128 * AROWB)      // 36864
#define AGG_SMEM (3 * STG_B)         // 110592

__global__ __launch_bounds__(256, 2)
void agg_mma(const float* __restrict__ Araw) {
    extern __shared__ __align__(16) char dsm[];
    const uint32_t sm0 = smem_u32(dsm);

    const int tid  = threadIdx.x;
    const int wid  = tid >> 5;
    const int lane = tid & 31;
    const int m0   = blockIdx.x * 128;
    const int n0   = blockIdx.y * 128;
    const int ksz  = blockIdx.z;
    const int kbase = ksz * (Nn / KSPLIT);   // 1024 per split

    const int wm = wid & 3;
    const int wn = wid >> 2;
    const int t  = lane & 3;
    const int g  = lane >> 2;

    const int a_off = (wm * 32 + (lane & 15)) * AROWB + (lane >> 4) * 16;
    const int b_off = (wn * 64 + (lane & 15)) * AROWB + (lane >> 4) * 16;

    float acc[2][8][4];
    #pragma unroll
    for (int mf = 0; mf < 2; mf++)
        #pragma unroll
        for (int nf = 0; nf < 8; nf++)
            #pragma unroll
            for (int q = 0; q < 4; q++) acc[mf][nf][q] = 0.0f;

    const int NKT = (Nn / KSPLIT) / 32;      // 32 chunks

    auto load_stage = [&](int slot, int kc) {
        const uint32_t stg = sm0 + slot * STG_B;
        const int k0 = kbase + kc * 32;
        #pragma unroll
        for (int i = 0; i < 4; i++) {
            int sid = tid + 256 * i;
            int r = sid >> 3, s = sid & 7;
            uint32_t soff = r * AROWB + s * 16;
            cpa16(stg + A_O + soff, Araw + (long long)(m0 + r) * Nn + k0 + s * 4);
            cpa16(stg + B_O + soff, g_Bt + (long long)(n0 + r) * Nn + k0 + s * 4);
        }
    };

    load_stage(0, 0); CP_COMMIT();
    load_stage(1, 1); CP_COMMIT();

    int slot = 0;
    for (int kc = 0; kc < NKT; kc++) {
        if (kc == NKT - 1) {
            asm volatile("cp.async.wait_group 0;" ::: "memory");
        } else {
            asm volatile("cp.async.wait_group 1;" ::: "memory");
        }
        __syncthreads();

        // issue next loads BEFORE compute; slot (kc+2)%3 was consumed at kc-1
        if (kc + 2 < NKT) {
            int ns = slot + 2; if (ns >= 3) ns -= 3;
            load_stage(ns, kc + 2);
            CP_COMMIT();
        }

        const uint32_t stg = sm0 + slot * STG_B;

        #pragma unroll
        for (int k8 = 0; k8 < 4; k8++) {
            const uint32_t ko = k8 * 32;

            uint32_t ar0[4], ar1[4];
            LDSM_X4(ar0[0], ar0[1], ar0[2], ar0[3], stg + A_O + a_off + ko);
            LDSM_X4(ar1[0], ar1[1], ar1[2], ar1[3],
                    stg + A_O + a_off + ko + 16 * AROWB);
            uint32_t ah[2][4];
            #pragma unroll
            for (int q = 0; q < 4; q++) {
                ah[0][q] = tf32u(ar0[q]);
                ah[1][q] = tf32u(ar1[q]);
            }

            #pragma unroll
            for (int nbi = 0; nbi < 4; nbi++) {
                uint32_t br[4];
                LDSM_X4(br[0], br[1], br[2], br[3],
                        stg + B_O + b_off + nbi * 16 * AROWB + ko);

                const int nf0 = nbi * 2;
                mma1688(acc[0][nf0 + 0], ah[0], br[0], br[2]);
                mma1688(acc[0][nf0 + 1], ah[0], br[1], br[3]);
                mma1688(acc[1][nf0 + 0], ah[1], br[0], br[2]);
                mma1688(acc[1][nf0 + 1], ah[1], br[1], br[3]);
            }
        }

        if (++slot == 3) slot = 0;
    }

    float* outp = g_part + (long long)ksz * (Nn * CC);
    const int c2 = t * 2;
    #pragma unroll
    for (int mf = 0; mf < 2; mf++) {
        #pragma unroll
        for (int nf = 0; nf < 8; nf++) {
            const int row = m0 + wm * 32 + mf * 16 + g;
            const int col = n0 + wn * 64 + nf * 8 + c2;
            *(float2*)&outp[(long long)row * CC + col] =
                make_float2(acc[mf][nf][0], acc[mf][nf][1]);
            *(float2*)&outp[(long long)(row + 8) * CC + col] =
                make_float2(acc[mf][nf][2], acc[mf][nf][3]);
        }
    }
}

// ---------------------------------------------------------------------------
// reduce_agg: g_agg = sum of KSPLIT partials
// ---------------------------------------------------------------------------
__global__ __launch_bounds__(256)
void reduce_agg() {
    const int i4 = blockIdx.x * 256 + threadIdx.x;
    const float4* P = (const float4*)g_part;
    const int S = (Nn * CC) / 4;
    float4 a = P[i4], b = P[S + i4], c = P[2 * S + i4], d = P[3 * S + i4];
    ((float4*)g_agg)[i4] = make_float4(a.x + b.x + c.x + d.x,
                                       a.y + b.y + c.y + d.y,
                                       a.z + b.z + c.z + d.z,
                                       a.w + b.w + c.w + d.w);
}

// ---------------------------------------------------------------------------
// gates via tensor cores: 1-pass (A rna-rounded in regs; W pre-rounded rna)
// ---------------------------------------------------------------------------
#define GA_ROWB 272                       // 64 fp32 + 16B pad
#define GSM_A   0
#define GSM_B   (64 * GA_ROWB)            // 17408
#define GSM_BIAS (GSM_B + 512 * 144)      // 91136
#define GSM_PRE  (GSM_BIAS + 2048)        // 93184
#define GATES_SMEM (GSM_PRE + 4 * 64 * 32 * 4)   // 125952

template <int NGATES, int WOFF>
__device__ __forceinline__ void gates_core(char* dsm, int idx0, int tid,
                                           const float* bias,
                                           float pre_out[2][4][4],
                                           int& wm_o, int& wn_o) {
    const uint32_t sm0 = smem_u32(dsm);
    const int wid  = tid >> 5;
    const int lane = tid & 31;
    const int wm = wid & 1;
    const int wn = wid >> 1;
    const int t  = lane & 3;
    wm_o = wm; wn_o = wn;

    #pragma unroll
    for (int i = 0; i < 4; i++) {
        int sid = tid + 256 * i;
        int r = sid >> 4, seg = sid & 15;
        int idx = idx0 + r;
        int b = idx >> 12, n = idx & (Nn - 1);
        int goff = n * CC + ((seg < 8) ? (b * 32 + seg * 4)
                                       : (128 + b * 32 + (seg - 8) * 4));
        cpa16(sm0 + GSM_A + r * GA_ROWB + seg * 16, g_agg + goff);
    }
    const int NB = NGATES * 128 * 8;
    for (int sid = tid; sid < NB; sid += 256) {
        int col = sid >> 3, seg = sid & 7;
        cpa16(sm0 + GSM_B + col * 144 + seg * 16,
              g_Wt + (WOFF + col) * 32 + seg * 4);
    }
    float* smBias = (float*)(dsm + GSM_BIAS);
    for (int colz = tid; colz < NGATES * 128; colz += 256)
        smBias[colz] = bias[WOFF + colz];
    CP_COMMIT(); CP_WAIT0();
    __syncthreads();

    float acc[2][16][4];
    #pragma unroll
    for (int mf = 0; mf < 2; mf++)
        #pragma unroll
        for (int nf = 0; nf < 16; nf++)
            #pragma unroll
            for (int q = 0; q < 4; q++) acc[mf][nf][q] = 0.0f;

    if (wn < NGATES) {
        const uint32_t a_base = sm0 + GSM_A +
            (wm * 32 + (lane & 15)) * GA_ROWB + (lane >> 4) * 16;
        const uint32_t b_base = sm0 + GSM_B +
            (wn * 128 + (lane & 15)) * 144 + (lane >> 4) * 16;

        #pragma unroll
        for (int k8 = 0; k8 < 4; k8++) {
            uint32_t arx0[4], arx1[4], arh0[4], arh1[4];
            LDSM_X4(arx0[0], arx0[1], arx0[2], arx0[3], a_base + k8 * 32);
            LDSM_X4(arx1[0], arx1[1], arx1[2], arx1[3],
                    a_base + k8 * 32 + 16 * GA_ROWB);
            LDSM_X4(arh0[0], arh0[1], arh0[2], arh0[3], a_base + 128 + k8 * 32);
            LDSM_X4(arh1[0], arh1[1], arh1[2], arh1[3],
                    a_base + 128 + k8 * 32 + 16 * GA_ROWB);
            uint32_t ax[2][4], ahh[2][4];
            #pragma unroll
            for (int q = 0; q < 4; q++) {
                ax[0][q]  = tf32u(arx0[q]);
                ax[1][q]  = tf32u(arx1[q]);
                ahh[0][q] = tf32u(arh0[q]);
                ahh[1][q] = tf32u(arh1[q]);
            }

            #pragma unroll
            for (int nbi = 0; nbi < 8; nbi++) {
                uint32_t br[4];
                LDSM_X4(br[0], br[1], br[2], br[3],
                        b_base + nbi * 16 * 144 + k8 * 32);

                const int nf0 = nbi * 2;
                uint32_t (*aH)[4] = (nbi < 4) ? ax : ahh;
                mma1688(acc[0][nf0 + 0], aH[0], br[0], br[2]);
                mma1688(acc[0][nf0 + 1], aH[0], br[1], br[3]);
                mma1688(acc[1][nf0 + 0], aH[1], br[0], br[2]);
                mma1688(acc[1][nf0 + 1], aH[1], br[1], br[3]);
            }
        }

        float bv[16][2];
        #pragma unroll
        for (int nf = 0; nf < 16; nf++)
            #pragma unroll
            for (int p = 0; p < 2; p++)
                bv[nf][p] = smBias[wn * 128 + nf * 8 + t * 2 + p];
        #pragma unroll
        for (int mf = 0; mf < 2; mf++)
            #pragma unroll
            for (int nf = 0; nf < 16; nf++)
                #pragma unroll
                for (int q = 0; q < 4; q++)
                    acc[mf][nf][q] += bv[nf][q & 1];

        #pragma unroll
        for (int mf = 0; mf < 2; mf++)
            #pragma unroll
            for (int nf = 0; nf < 4; nf++)
                #pragma unroll
                for (int q = 0; q < 4; q++)
                    pre_out[mf][nf][q] =
                        acc[mf][nf][q]      * sigm(acc[mf][nf + 4][q]) +
                        acc[mf][nf + 8][q]  * sigm(acc[mf][nf + 12][q]);
    }
}

__global__ __launch_bounds__(256, 1)
void gates1_mma(const float* __restrict__ c_in,
                const float* __restrict__ bias,
                float* __restrict__ c_out)
{
    extern __shared__ __align__(16) char dsm[];
    const int tid  = threadIdx.x;
    const int lane = tid & 31;
    const int idx0 = blockIdx.x * 64;

    float pre[2][4][4];
    int wm, wn;
    gates_core<4, 0>(dsm, idx0, tid, bias, pre, wm, wn);

    float* smPre = (float*)(dsm + GSM_PRE);
    {
        const int t = lane & 3, g = lane >> 2;
        #pragma unroll
        for (int mf = 0; mf < 2; mf++)
            #pragma unroll
            for (int nf = 0; nf < 4; nf++)
                #pragma unroll
                for (int q = 0; q < 4; q++) {
                    int row = wm * 32 + mf * 16 + g + ((q >> 1) ? 8 : 0);
                    int j = nf * 8 + t * 2 + (q & 1);
                    smPre[wn * 2048 + row * 32 + j] = pre[mf][nf][q];
                }
    }
    __syncthreads();

    #pragma unroll
    for (int u = 0; u < 8; u++) {
        int cell = tid + 256 * u;
        float pf = smPre[cell];
        float pi = smPre[2048 + cell];
        float pc = smPre[2 * 2048 + cell];
        float po = smPre[3 * 2048 + cell];
        float cn = sigm(pf) * c_in[(long long)idx0 * 32 + cell] +
                   sigm(pi) * tanhf(pc);
        c_out[(long long)idx0 * 32 + cell] = cn;
        g_h1[(long long)idx0 * 32 + cell] = sigm(po) * tanhf(cn);
    }
}

__global__ __launch_bounds__(256, 1)
void gates2_mma(const float* __restrict__ m_in,
                const float* __restrict__ bias,
                float* __restrict__ h_out,
                float* __restrict__ m_out)
{
    extern __shared__ __align__(16) char dsm[];
    const int tid  = threadIdx.x;
    const int lane = tid & 31;
    const int idx0 = blockIdx.x * 64;

    float pre[2][4][4];
    int wm, wn;
    gates_core<3, 512>(dsm, idx0, tid, bias, pre, wm, wn);

    float* smPre = (float*)(dsm + GSM_PRE);
    if (wn < 3) {
        const int t = lane & 3, g = lane >> 2;
        #pragma unroll
        for (int mf = 0; mf < 2; mf++)
            #pragma unroll
            for (int nf = 0; nf < 4; nf++)
                #pragma unroll
                for (int q = 0; q < 4; q++) {
                    int row = wm * 32 + mf * 16 + g + ((q >> 1) ? 8 : 0);
                    int j = nf * 8 + t * 2 + (q & 1);
                    smPre[wn * 2048 + row * 32 + j] = pre[mf][nf][q];
                }
    }
    __syncthreads();

    #pragma unroll
    for (int u = 0; u < 8; u++) {
        int cell = tid + 256 * u;
        float i2 = sigm(smPre[cell]);
        float gg = sigm(smPre[2048 + cell]);
        float o2 = sigm(smPre[2 * 2048 + cell]);
        float mn = i2 * m_in[(long long)idx0 * 32 + cell] + (1.0f - i2) * gg;
        m_out[(long long)idx0 * 32 + cell] = mn;
        h_out[(long long)idx0 * 32 + cell] = mn * o2;
    }
}

// ---------------------------------------------------------------------------
// Launch
// ---------------------------------------------------------------------------
extern "C" void kernel_launch(void* const* d_in, const int* in_sizes, int n_in,
                              void* d_out, int out_size) {
    const float* x    = (const float*)d_in[0];
    const float* h    = (const float*)d_in[1];
    const float* c    = (const float*)d_in[2];
    const float* m    = (const float*)d_in[3];
    const float* adj  = (const float*)d_in[4];
    const float* W    = (const float*)d_in[5];
    const float* bias = (const float*)d_in[6];

    float* out   = (float*)d_out;
    float* h_out = out;               // h_new
    float* c_out = out + BNF;         // c_new
    float* m_out = out + 2 * BNF;     // m_new

    cudaFuncSetAttribute(agg_mma, cudaFuncAttributeMaxDynamicSharedMemorySize, AGG_SMEM);
    cudaFuncSetAttribute(gates1_mma, cudaFuncAttributeMaxDynamicSharedMemorySize, GATES_SMEM);
    cudaFuncSetAttribute(gates2_mma, cudaFuncAttributeMaxDynamicSharedMemorySize, GATES_SMEM);

    prep_Wt<<<112, 256>>>(W);

    dim3 agrid(32, 2, KSPLIT);   // 256 CTAs -> one wave at 2 CTAs/SM

    // Phase 1
    conv_rhs<<<dim3(64, 8), 256>>>(x, h, 0);
    agg_mma<<<agrid, 256, AGG_SMEM>>>(adj);
    reduce_agg<<<1024, 256>>>();
    gates1_mma<<<256, 256, GATES_SMEM>>>(c, bias, c_out);

    // Phase 2
    conv_rhs<<<dim3(64, 8), 256>>>(nullptr, m, 1);
    agg_mma<<<agrid, 256, AGG_SMEM>>>(adj);
    reduce_agg<<<1024, 256>>>();
    gates2_mma<<<256, 256, GATES_SMEM>>>(m, bias, h_out, m_out);
}